// round 6
// baseline (speedup 1.0000x reference)
#include <cuda_runtime.h>

// NCC: image (8,3,1024,1024) f32, template (3,31,31) f32, stride 1, pad 15.
// out (8,1024,1024) f32 = mean_c[ conv(img, norm_t) / (sqrt(m2-m1^2)+eps) ], NaN->0
//
// R6 = R5 resubmitted verbatim (R5 never ran: broker container failure).
//   ncc_denom : fused tile-local separable 31x31 box sums -> g_R = 1/(sqrt(var)+eps)
//   ncc_prep  : normalize template -> g_tA (aligned) + g_tB (shift-1) copies
//   ncc_main  : template correlation (fma.rn.f32x2) * g_R; 64x32 tile, 8x2 px/thread
//               launch_bounds (128,3) => ~168 regs, no spills, 12 warps/SM

#define EPSF 1e-9f
#define INV961 (1.0f/961.0f)
#define PLANE_ELEMS (24*1024*1024)

__device__ float g_tA[3][31][32];
__device__ float g_tB[3][31][32];
__device__ float g_R [PLANE_ELEMS];

__device__ __forceinline__ void dfma(float2 &d, const float2 a, const float2 b) {
    asm("fma.rn.f32x2 %0, %1, %2, %0;"
        : "+l"(reinterpret_cast<unsigned long long &>(d))
        : "l"(reinterpret_cast<const unsigned long long &>(a)),
          "l"(reinterpret_cast<const unsigned long long &>(b)));
}

// ---------------------------------------------------------------- template prep
__global__ void ncc_prep(const float* __restrict__ t) {
    const int c = blockIdx.x;
    const int lane = threadIdx.x;
    const float* tc = t + c * 961;
    float s = 0.f;
    for (int i = lane; i < 961; i += 32) s += tc[i];
#pragma unroll
    for (int o = 16; o > 0; o >>= 1) s += __shfl_xor_sync(0xffffffffu, s, o);
    const float mu = s * INV961;
    float v = 0.f;
    for (int i = lane; i < 961; i += 32) { float d = tc[i] - mu; v = fmaf(d, d, v); }
#pragma unroll
    for (int o = 16; o > 0; o >>= 1) v += __shfl_xor_sync(0xffffffffu, v, o);
    const float sd = sqrtf(v * INV961);
    const float scale = 1.f / ((sd + EPSF) * 961.f);
    for (int idx = lane; idx < 31 * 32; idx += 32) {
        const int ri = idx >> 5, j = idx & 31;
        g_tA[c][ri][j] = (j < 31) ? (tc[ri * 31 + j] - mu) * scale : 0.f;
        g_tB[c][ri][j] = (j < 30) ? (tc[ri * 31 + j + 1] - mu) * scale : 0.f;
    }
}

// ---------------------------------------------------------------- fused denominator
// one block per 32x32 output tile per plane; 256 threads.
__global__ __launch_bounds__(256)
void ncc_denom(const float* __restrict__ img) {
    __shared__ float halo[62][65];   // stride 65 -> conflict-free row walks
    __shared__ float h1[62][32];
    __shared__ float h2[62][32];
    const int tid = threadIdx.x;
    const int gx0 = blockIdx.x << 5, gy0 = blockIdx.y << 5, pl = blockIdx.z;
    const float* plane = img + ((size_t)pl << 20);

    // load 62x62 halo (zero outside image)
    {
        const int col = tid & 63;
        const int gx = gx0 - 15 + col;
        const bool xok = (col < 62) && ((unsigned)gx < 1024u);
#pragma unroll 1
        for (int r = tid >> 6; r < 62; r += 4) {
            const int gy = gy0 - 15 + r;
            float v = 0.f;
            if (xok && ((unsigned)gy < 1024u)) v = plane[((size_t)gy << 10) + gx];
            halo[r][col] = v;
        }
    }
    __syncthreads();

    // horizontal sliding 31-box per row (62 rows x {sum, sumsq})
    if (tid < 124) {
        const int r = tid >> 1;
        if ((tid & 1) == 0) {
            float s = 0.f;
#pragma unroll
            for (int j = 0; j < 31; ++j) s += halo[r][j];
            h1[r][0] = s;
#pragma unroll 1
            for (int x = 1; x < 32; ++x) { s += halo[r][x + 30] - halo[r][x - 1]; h1[r][x] = s; }
        } else {
            float s = 0.f;
#pragma unroll
            for (int j = 0; j < 31; ++j) { const float f = halo[r][j]; s = fmaf(f, f, s); }
            h2[r][0] = s;
#pragma unroll 1
            for (int x = 1; x < 32; ++x) {
                const float fn = halo[r][x + 30], fo = halo[r][x - 1];
                s += fn * fn - fo * fo;
                h2[r][x] = s;
            }
        }
    }
    __syncthreads();

    // vertical sliding 31-box + finalize; warp 0, thread = column (coalesced stores)
    if (tid < 32) {
        float S1 = 0.f, S2 = 0.f;
#pragma unroll 1
        for (int r = 0; r < 31; ++r) { S1 += h1[r][tid]; S2 += h2[r][tid]; }
        float* Rp = g_R + ((size_t)pl << 20) + ((size_t)gy0 << 10) + gx0 + tid;
#pragma unroll 1
        for (int y = 0; y < 32; ++y) {
            const float m1 = S1 * INV961;
            const float var = fmaf(-m1, m1, S2 * INV961);
            Rp[(size_t)y << 10] = 1.f / (sqrtf(var) + EPSF);   // var<0 -> NaN propagates
            if (y < 31) {
                S1 += h1[y + 31][tid] - h1[y][tid];
                S2 += h2[y + 31][tid] - h2[y][tid];
            }
        }
    }
}

// ---------------------------------------------------------------- main correlation
__global__ __launch_bounds__(128, 3)
void ncc_main(const float* __restrict__ img, float* __restrict__ out) {
    __shared__ __align__(16) float sh_halo[62][100];    // cols 0..95 valid, stride 100
    __shared__ __align__(16) float sh_tA[31 * 32];
    __shared__ __align__(16) float sh_tB[31 * 32];

    const int tx = threadIdx.x;           // 0..7
    const int ty = threadIdx.y;           // 0..15
    const int tid = ty * 8 + tx;
    const int bx = blockIdx.x, by = blockIdx.y, n = blockIdx.z;
    const int gx0 = bx << 6, gy0 = by << 5;
    const int x0 = tx << 3, y0 = ty << 1;  // 8 wide x 2 tall per thread

    float oacc[2][8];
#pragma unroll
    for (int p = 0; p < 2; ++p)
#pragma unroll
        for (int k = 0; k < 8; ++k) oacc[p][k] = 0.f;

    for (int c = 0; c < 3; ++c) {
        __syncthreads();
        // templates
        {
            const float* gA = &g_tA[c][0][0];
            const float* gB = &g_tB[c][0][0];
#pragma unroll
            for (int i = 0; i < 8; ++i) {
                const int idx = tid + (i << 7);
                if (idx < 992) { sh_tA[idx] = gA[idx]; sh_tB[idx] = gB[idx]; }
            }
        }
        // halo: 62 rows x 96 cols (zero outside image)
        if (tid < 96) {
            const float* plane = img + ((size_t)(n * 3 + c) << 20);
            const int gx = gx0 - 15 + tid;
            const bool xok = (unsigned)gx < 1024u;
#pragma unroll 1
            for (int r = 0; r < 62; ++r) {
                const int gy = gy0 - 15 + r;
                float v = 0.f;
                if (xok && ((unsigned)gy < 1024u)) v = plane[((size_t)gy << 10) + gx];
                sh_halo[r][tid] = v;
            }
        }
        __syncthreads();

        float2 acc[2][8];
#pragma unroll
        for (int p = 0; p < 2; ++p)
#pragma unroll
            for (int k = 0; k < 8; ++k) acc[p][k] = make_float2(0.f, 0.f);

        // r = 0..31: p=0 uses i=r (0..30, skip 31); p=1 uses i=r-1 (0..30)
#pragma unroll 1
        for (int r = 0; r < 32; ++r) {
            const float* hrow = &sh_halo[y0 + r][x0];
            float4 Wv[10];
#pragma unroll
            for (int q = 0; q < 10; ++q) Wv[q] = *(const float4*)(hrow + (q << 2));
#pragma unroll
            for (int p = 0; p < 2; ++p) {
                const int i = r - p;
                if ((unsigned)i > 30u) continue;
                const float4* TA = (const float4*)(sh_tA + (i << 5));
                const float4* TB = (const float4*)(sh_tB + (i << 5));
                const float t0 = sh_tA[i << 5];
                float2 a0 = acc[p][0], a1 = acc[p][1], a2 = acc[p][2], a3 = acc[p][3];
                float2 a4 = acc[p][4], a5 = acc[p][5], a6 = acc[p][6], a7 = acc[p][7];
#pragma unroll
                for (int q = 0; q < 8; ++q) {
                    const float4 ta = TA[q], tb = TB[q];
                    const float2 A0 = make_float2(ta.x, ta.y), A1 = make_float2(ta.z, ta.w);
                    const float2 B0 = make_float2(tb.x, tb.y), B1 = make_float2(tb.z, tb.w);
                    const float2 P0 = make_float2(Wv[q].x,   Wv[q].y);
                    const float2 P1 = make_float2(Wv[q].z,   Wv[q].w);
                    const float2 P2 = make_float2(Wv[q+1].x, Wv[q+1].y);
                    const float2 P3 = make_float2(Wv[q+1].z, Wv[q+1].w);
                    const float2 P4 = make_float2(Wv[q+2].x, Wv[q+2].y);
                    const float2 P5 = make_float2(Wv[q+2].z, Wv[q+2].w);
                    dfma(a0, P0, A0); dfma(a2, P1, A0); dfma(a4, P2, A0); dfma(a6, P3, A0);
                    dfma(a1, P1, B0); dfma(a3, P2, B0); dfma(a5, P3, B0); dfma(a7, P4, B0);
                    dfma(a0, P1, A1); dfma(a2, P2, A1); dfma(a4, P3, A1); dfma(a6, P4, A1);
                    dfma(a1, P2, B1); dfma(a3, P3, B1); dfma(a5, P4, B1); dfma(a7, P5, B1);
                }
                a1.x = fmaf(Wv[0].y, t0, a1.x);   // odd pixels' tap-0 scalar
                a3.x = fmaf(Wv[0].w, t0, a3.x);
                a5.x = fmaf(Wv[1].y, t0, a5.x);
                a7.x = fmaf(Wv[1].w, t0, a7.x);
                acc[p][0] = a0; acc[p][1] = a1; acc[p][2] = a2; acc[p][3] = a3;
                acc[p][4] = a4; acc[p][5] = a5; acc[p][6] = a6; acc[p][7] = a7;
            }
        }

        // combine with precomputed reciprocal denominator
        {
            const float* Rpl = g_R + ((size_t)(n * 3 + c) << 20);
#pragma unroll
            for (int p = 0; p < 2; ++p) {
                const int gy = gy0 + y0 + p;
                const float* rp = Rpl + ((size_t)gy << 10) + gx0 + x0;
                const float4 r0 = *(const float4*)rp;
                const float4 r1 = *(const float4*)(rp + 4);
                oacc[p][0] += (acc[p][0].x + acc[p][0].y) * r0.x;
                oacc[p][1] += (acc[p][1].x + acc[p][1].y) * r0.y;
                oacc[p][2] += (acc[p][2].x + acc[p][2].y) * r0.z;
                oacc[p][3] += (acc[p][3].x + acc[p][3].y) * r0.w;
                oacc[p][4] += (acc[p][4].x + acc[p][4].y) * r1.x;
                oacc[p][5] += (acc[p][5].x + acc[p][5].y) * r1.y;
                oacc[p][6] += (acc[p][6].x + acc[p][6].y) * r1.z;
                oacc[p][7] += (acc[p][7].x + acc[p][7].y) * r1.w;
            }
        }
    }

    // write out: mean over channels, NaN -> 0
#pragma unroll
    for (int p = 0; p < 2; ++p) {
        float v[8];
#pragma unroll
        for (int k = 0; k < 8; ++k) {
            const float r = oacc[p][k] * (1.0f / 3.0f);
            v[k] = (r == r) ? r : 0.f;
        }
        float* dst = out + (((size_t)n << 20) + ((size_t)(gy0 + y0 + p) << 10) + gx0 + x0);
        *(float4*)dst       = make_float4(v[0], v[1], v[2], v[3]);
        *(float4*)(dst + 4) = make_float4(v[4], v[5], v[6], v[7]);
    }
}

extern "C" void kernel_launch(void* const* d_in, const int* in_sizes, int n_in,
                              void* d_out, int out_size) {
    (void)in_sizes; (void)n_in; (void)out_size;
    const float* img  = (const float*)d_in[0];
    const float* tmpl = (const float*)d_in[1];
    float* out = (float*)d_out;

    // denom first (template-independent), then prep, then main (needs both).
    // This also places ncc_main at launch index 5 (0-based) for ncu -s 5 -c 1.
    ncc_denom<<<dim3(32, 32, 24), 256>>>(img);
    ncc_prep<<<3, 32>>>(tmpl);
    ncc_main<<<dim3(16, 32, 8), dim3(8, 16)>>>(img, out);
}

// round 8
// speedup vs baseline: 1.3072x; 1.3072x over previous
#include <cuda_runtime.h>

// NCC: image (8,3,1024,1024) f32, template (3,31,31) f32, stride 1, pad 15.
// out (8,1024,1024) f32 = mean_c[ conv(img, norm_t) / (sqrt(m2-m1^2)+eps) ], NaN->0
//
// R8 = R7 resubmitted verbatim (R7 never ran: broker container failure).
//   ncc_aux  : (a) 192 blocks: streaming denominator. Per block: one plane x 128-row
//              segment, full 1024-col width. Column sums C1/C2 in bank-padded smem,
//              vertical slide via +row/-row gmem reads, horizontal 31-box via
//              per-thread 4-wide slide. Writes g_R = 1/(sqrt(var)+eps) (NaN propagates).
//              (b) 3 blocks: template normalization -> g_tA (aligned) + g_tB (shift-1).
//   ncc_main : template correlation, all fma.rn.f32x2, 64x32 tile, 8x2 px/thread,
//              sliding 3-float4 image window (low regs) -> (128,4), 16 warps/SM.

#define EPSF 1e-9f
#define INV961 (1.0f/961.0f)
#define PLANE_ELEMS (24*1024*1024)

__device__ float g_tA[3][31][32];
__device__ float g_tB[3][31][32];
__device__ float g_R [PLANE_ELEMS];

__device__ __forceinline__ void dfma(float2 &d, const float2 a, const float2 b) {
    asm("fma.rn.f32x2 %0, %1, %2, %0;"
        : "+l"(reinterpret_cast<unsigned long long &>(d))
        : "l"(reinterpret_cast<const unsigned long long &>(a)),
          "l"(reinterpret_cast<const unsigned long long &>(b)));
}

// ---------------------------------------------------------------- aux: denom + prep
// C entry ci (0..1053) <-> image col ci-15. Padded smem index: ci + (ci>>2)
// (stride 5 per thread across the warp -> conflict-free, gcd(5,32)=1).
__global__ __launch_bounds__(256)
void ncc_aux(const float* __restrict__ img, const float* __restrict__ t) {
    const int b = blockIdx.x;
    const int tid = threadIdx.x;

    if (b >= 192) {                       // ---- template prep (3 blocks, warp 0) ----
        if (tid >= 32) return;
        const int c = b - 192;
        const int lane = tid;
        const float* tc = t + c * 961;
        float s = 0.f;
        for (int i = lane; i < 961; i += 32) s += tc[i];
#pragma unroll
        for (int o = 16; o > 0; o >>= 1) s += __shfl_xor_sync(0xffffffffu, s, o);
        const float mu = s * INV961;
        float v = 0.f;
        for (int i = lane; i < 961; i += 32) { float d = tc[i] - mu; v = fmaf(d, d, v); }
#pragma unroll
        for (int o = 16; o > 0; o >>= 1) v += __shfl_xor_sync(0xffffffffu, v, o);
        const float sd = sqrtf(v * INV961);
        const float scale = 1.f / ((sd + EPSF) * 961.f);
        for (int idx = lane; idx < 31 * 32; idx += 32) {
            const int ri = idx >> 5, j = idx & 31;
            g_tA[c][ri][j] = (j < 31) ? (tc[ri * 31 + j] - mu) * scale : 0.f;
            g_tB[c][ri][j] = (j < 30) ? (tc[ri * 31 + j + 1] - mu) * scale : 0.f;
        }
        return;
    }

    // ---- streaming denominator ----
    __shared__ float C1[1320];
    __shared__ float C2[1320];
    const int pl = b >> 3, seg = b & 7;
    const int ry0 = seg << 7;
    const float* plane = img + ((size_t)pl << 20);

    for (int i = tid; i < 1320; i += 256) { C1[i] = 0.f; C2[i] = 0.f; }
    __syncthreads();

    // init window rows [ry0-15, ry0+15]; each C entry owned by one thread (ci % 256)
    for (int r = ry0 - 15; r <= ry0 + 15; ++r) {
        if ((unsigned)r >= 1024u) continue;
        const float* row = plane + ((size_t)r << 10);
        for (int ci = tid; ci < 1054; ci += 256) {
            const int col = ci - 15;
            if ((unsigned)col < 1024u) {
                const float v = row[col];
                const int pi = ci + (ci >> 2);
                C1[pi] += v;
                C2[pi] = fmaf(v, v, C2[pi]);
            }
        }
    }
    __syncthreads();

    const int x0 = tid << 2;
    float* Rseg = g_R + ((size_t)pl << 20) + x0;

#pragma unroll 1
    for (int y = ry0; y < ry0 + 128; ++y) {
        // horizontal 31-box with 4-wide slide; accumulate on the fly
        float S = 0.f, Q = 0.f, a0, a1, a2, b0, b1, b2;
#pragma unroll
        for (int j = 0; j < 31; ++j) {
            const int ci = x0 + j;
            const int pi = ci + (ci >> 2);
            const float c1v = C1[pi], c2v = C2[pi];
            S += c1v; Q += c2v;
            if (j == 0) { a0 = c1v; b0 = c2v; }
            if (j == 1) { a1 = c1v; b1 = c2v; }
            if (j == 2) { a2 = c1v; b2 = c2v; }
        }
        float n0, n1, n2, m0, m1v, m2v;
        {
            const int c31 = x0 + 31, c32 = x0 + 32, c33 = x0 + 33;
            n0 = C1[c31 + (c31 >> 2)]; m0  = C2[c31 + (c31 >> 2)];
            n1 = C1[c32 + (c32 >> 2)]; m1v = C2[c32 + (c32 >> 2)];
            n2 = C1[c33 + (c33 >> 2)]; m2v = C2[c33 + (c33 >> 2)];
        }
        const float s0 = S,            q0 = Q;
        const float s1 = s0 - a0 + n0, q1 = q0 - b0 + m0;
        const float s2 = s1 - a1 + n1, q2 = q1 - b1 + m1v;
        const float s3 = s2 - a2 + n2, q3 = q2 - b2 + m2v;

        float4 rv;
        { const float m = s0 * INV961; rv.x = 1.f / (sqrtf(fmaf(-m, m, q0 * INV961)) + EPSF); }
        { const float m = s1 * INV961; rv.y = 1.f / (sqrtf(fmaf(-m, m, q1 * INV961)) + EPSF); }
        { const float m = s2 * INV961; rv.z = 1.f / (sqrtf(fmaf(-m, m, q2 * INV961)) + EPSF); }
        { const float m = s3 * INV961; rv.w = 1.f / (sqrtf(fmaf(-m, m, q3 * INV961)) + EPSF); }
        *(float4*)(Rseg + ((size_t)y << 10)) = rv;

        __syncthreads();   // all reads of C done before owners update
        // slide window: add row y+16, subtract row y-15
        {
            const int ya = y + 16, ys = y - 15;
            const float* rowa = plane + ((size_t)ya << 10);
            const float* rows = plane + ((size_t)ys << 10);
            const bool va = (ya < 1024), vs = (ys >= 0);
            for (int ci = tid; ci < 1054; ci += 256) {
                const int col = ci - 15;
                if ((unsigned)col < 1024u) {
                    const float fa = va ? rowa[col] : 0.f;
                    const float fs = vs ? rows[col] : 0.f;
                    const int pi = ci + (ci >> 2);
                    C1[pi] += fa - fs;
                    C2[pi] += fa * fa - fs * fs;
                }
            }
        }
        __syncthreads();   // updates visible before next row's reads
    }
}

// ---------------------------------------------------------------- correlation row body
template<int DOP0, int DOP1>
__device__ __forceinline__ void corr_row2(
    const float* __restrict__ hrow,
    const float* __restrict__ tA0, const float* __restrict__ tB0,
    const float* __restrict__ tA1, const float* __restrict__ tB1,
    float2* __restrict__ acc0, float2* __restrict__ acc1)
{
    float4 W0 = *(const float4*)(hrow);
    float4 W1 = *(const float4*)(hrow + 4);
    const float w1s = W0.y, w3s = W0.w, w5s = W1.y, w7s = W1.w;
#pragma unroll
    for (int q = 0; q < 8; ++q) {
        const float4 W2 = *(const float4*)(hrow + 8 + (q << 2));
        const float2 P0 = make_float2(W0.x, W0.y), P1 = make_float2(W0.z, W0.w);
        const float2 P2 = make_float2(W1.x, W1.y), P3 = make_float2(W1.z, W1.w);
        const float2 P4 = make_float2(W2.x, W2.y), P5 = make_float2(W2.z, W2.w);
        if (DOP0) {
            const float4 ta = ((const float4*)tA0)[q];
            const float4 tb = ((const float4*)tB0)[q];
            const float2 A0 = make_float2(ta.x, ta.y), A1 = make_float2(ta.z, ta.w);
            const float2 B0 = make_float2(tb.x, tb.y), B1 = make_float2(tb.z, tb.w);
            dfma(acc0[0], P0, A0); dfma(acc0[2], P1, A0); dfma(acc0[4], P2, A0); dfma(acc0[6], P3, A0);
            dfma(acc0[1], P1, B0); dfma(acc0[3], P2, B0); dfma(acc0[5], P3, B0); dfma(acc0[7], P4, B0);
            dfma(acc0[0], P1, A1); dfma(acc0[2], P2, A1); dfma(acc0[4], P3, A1); dfma(acc0[6], P4, A1);
            dfma(acc0[1], P2, B1); dfma(acc0[3], P3, B1); dfma(acc0[5], P4, B1); dfma(acc0[7], P5, B1);
        }
        if (DOP1) {
            const float4 ta = ((const float4*)tA1)[q];
            const float4 tb = ((const float4*)tB1)[q];
            const float2 A0 = make_float2(ta.x, ta.y), A1 = make_float2(ta.z, ta.w);
            const float2 B0 = make_float2(tb.x, tb.y), B1 = make_float2(tb.z, tb.w);
            dfma(acc1[0], P0, A0); dfma(acc1[2], P1, A0); dfma(acc1[4], P2, A0); dfma(acc1[6], P3, A0);
            dfma(acc1[1], P1, B0); dfma(acc1[3], P2, B0); dfma(acc1[5], P3, B0); dfma(acc1[7], P4, B0);
            dfma(acc1[0], P1, A1); dfma(acc1[2], P2, A1); dfma(acc1[4], P3, A1); dfma(acc1[6], P4, A1);
            dfma(acc1[1], P2, B1); dfma(acc1[3], P3, B1); dfma(acc1[5], P4, B1); dfma(acc1[7], P5, B1);
        }
        W0 = W1; W1 = W2;
    }
    if (DOP0) {
        const float t0 = tA0[0];   // tap(0) scalar for odd pixels (shifted template)
        acc0[1].x = fmaf(w1s, t0, acc0[1].x);
        acc0[3].x = fmaf(w3s, t0, acc0[3].x);
        acc0[5].x = fmaf(w5s, t0, acc0[5].x);
        acc0[7].x = fmaf(w7s, t0, acc0[7].x);
    }
    if (DOP1) {
        const float t0 = tA1[0];
        acc1[1].x = fmaf(w1s, t0, acc1[1].x);
        acc1[3].x = fmaf(w3s, t0, acc1[3].x);
        acc1[5].x = fmaf(w5s, t0, acc1[5].x);
        acc1[7].x = fmaf(w7s, t0, acc1[7].x);
    }
}

// ---------------------------------------------------------------- main correlation
__global__ __launch_bounds__(128, 4)
void ncc_main(const float* __restrict__ img, float* __restrict__ out) {
    __shared__ __align__(16) float sh_halo[62][100];    // cols 0..95 valid, stride 100
    __shared__ __align__(16) float sh_tA[31 * 32];
    __shared__ __align__(16) float sh_tB[31 * 32];

    const int tx = threadIdx.x;           // 0..7
    const int ty = threadIdx.y;           // 0..15
    const int tid = ty * 8 + tx;
    const int bx = blockIdx.x, by = blockIdx.y, n = blockIdx.z;
    const int gx0 = bx << 6, gy0 = by << 5;
    const int x0 = tx << 3, y0 = ty << 1;  // 8 wide x 2 tall per thread

    float oacc[2][8];
#pragma unroll
    for (int p = 0; p < 2; ++p)
#pragma unroll
        for (int k = 0; k < 8; ++k) oacc[p][k] = 0.f;

    for (int c = 0; c < 3; ++c) {
        __syncthreads();
        // templates
        {
            const float* gA = &g_tA[c][0][0];
            const float* gB = &g_tB[c][0][0];
#pragma unroll
            for (int i = 0; i < 8; ++i) {
                const int idx = tid + (i << 7);
                if (idx < 992) { sh_tA[idx] = gA[idx]; sh_tB[idx] = gB[idx]; }
            }
        }
        // halo: 62 rows x 96 cols (zero outside image)
        if (tid < 96) {
            const float* plane = img + ((size_t)(n * 3 + c) << 20);
            const int gx = gx0 - 15 + tid;
            const bool xok = (unsigned)gx < 1024u;
#pragma unroll 1
            for (int r = 0; r < 62; ++r) {
                const int gy = gy0 - 15 + r;
                float v = 0.f;
                if (xok && ((unsigned)gy < 1024u)) v = plane[((size_t)gy << 10) + gx];
                sh_halo[r][tid] = v;
            }
        }
        __syncthreads();

        float2 acc0[8], acc1[8];
#pragma unroll
        for (int k = 0; k < 8; ++k) { acc0[k] = make_float2(0.f, 0.f); acc1[k] = make_float2(0.f, 0.f); }

        // r=0: only p=0 (template row 0); r=1..30: both; r=31: only p=1 (template row 30)
        corr_row2<1, 0>(&sh_halo[y0][x0], sh_tA, sh_tB, sh_tA, sh_tB, acc0, acc1);
#pragma unroll 1
        for (int r = 1; r < 31; ++r) {
            corr_row2<1, 1>(&sh_halo[y0 + r][x0],
                            sh_tA + (r << 5), sh_tB + (r << 5),
                            sh_tA + ((r - 1) << 5), sh_tB + ((r - 1) << 5),
                            acc0, acc1);
        }
        corr_row2<0, 1>(&sh_halo[y0 + 31][x0], sh_tA, sh_tB,
                        sh_tA + (30 << 5), sh_tB + (30 << 5), acc0, acc1);

        // combine with precomputed reciprocal denominator
        {
            const float* Rpl = g_R + ((size_t)(n * 3 + c) << 20);
            {
                const float* rp = Rpl + ((size_t)(gy0 + y0) << 10) + gx0 + x0;
                const float4 r0 = *(const float4*)rp;
                const float4 r1 = *(const float4*)(rp + 4);
                oacc[0][0] += (acc0[0].x + acc0[0].y) * r0.x;
                oacc[0][1] += (acc0[1].x + acc0[1].y) * r0.y;
                oacc[0][2] += (acc0[2].x + acc0[2].y) * r0.z;
                oacc[0][3] += (acc0[3].x + acc0[3].y) * r0.w;
                oacc[0][4] += (acc0[4].x + acc0[4].y) * r1.x;
                oacc[0][5] += (acc0[5].x + acc0[5].y) * r1.y;
                oacc[0][6] += (acc0[6].x + acc0[6].y) * r1.z;
                oacc[0][7] += (acc0[7].x + acc0[7].y) * r1.w;
            }
            {
                const float* rp = Rpl + ((size_t)(gy0 + y0 + 1) << 10) + gx0 + x0;
                const float4 r0 = *(const float4*)rp;
                const float4 r1 = *(const float4*)(rp + 4);
                oacc[1][0] += (acc1[0].x + acc1[0].y) * r0.x;
                oacc[1][1] += (acc1[1].x + acc1[1].y) * r0.y;
                oacc[1][2] += (acc1[2].x + acc1[2].y) * r0.z;
                oacc[1][3] += (acc1[3].x + acc1[3].y) * r0.w;
                oacc[1][4] += (acc1[4].x + acc1[4].y) * r1.x;
                oacc[1][5] += (acc1[5].x + acc1[5].y) * r1.y;
                oacc[1][6] += (acc1[6].x + acc1[6].y) * r1.z;
                oacc[1][7] += (acc1[7].x + acc1[7].y) * r1.w;
            }
        }
    }

    // write out: mean over channels, NaN -> 0
#pragma unroll
    for (int p = 0; p < 2; ++p) {
        float v[8];
#pragma unroll
        for (int k = 0; k < 8; ++k) {
            const float r = oacc[p][k] * (1.0f / 3.0f);
            v[k] = (r == r) ? r : 0.f;
        }
        float* dst = out + (((size_t)n << 20) + ((size_t)(gy0 + y0 + p) << 10) + gx0 + x0);
        *(float4*)dst       = make_float4(v[0], v[1], v[2], v[3]);
        *(float4*)(dst + 4) = make_float4(v[4], v[5], v[6], v[7]);
    }
}

extern "C" void kernel_launch(void* const* d_in, const int* in_sizes, int n_in,
                              void* d_out, int out_size) {
    (void)in_sizes; (void)n_in; (void)out_size;
    const float* img  = (const float*)d_in[0];
    const float* tmpl = (const float*)d_in[1];
    float* out = (float*)d_out;

    ncc_aux<<<195, 256>>>(img, tmpl);                       // denom (192) + prep (3)
    ncc_main<<<dim3(16, 32, 8), dim3(8, 16)>>>(img, out);
}

// round 10
// speedup vs baseline: 1.3151x; 1.0060x over previous
#include <cuda_runtime.h>

// NCC: image (8,3,1024,1024) f32, template (3,31,31) f32, stride 1, pad 15.
// out (8,1024,1024) f32 = mean_c[ conv(img, norm_t) / (sqrt(m2-m1^2)+eps) ], NaN->0
//
// R10 = R9 resubmitted verbatim (R9 never ran: broker container failure).
//   ncc_aux  : 192 blocks streaming denominator -> g_R ; 3 blocks template prep -> g_tA/g_tB
//   (memcpy) : g_tA/g_tB -> __constant__ c_tA/c_tB (graph-legal D2D async copy)
//   ncc_main : correlation, all fma.rn.f32x2; image rows via sliding 3-float4 smem window,
//              template rows via LDC from constant memory. 64x32 tile, 8x2 px/thread.

#define EPSF 1e-9f
#define INV961 (1.0f/961.0f)
#define PLANE_ELEMS (24*1024*1024)
#define TSZ (3*31*32)

__device__ float g_tA[TSZ];
__device__ float g_tB[TSZ];
__device__ float g_R [PLANE_ELEMS];

__constant__ float c_tA[TSZ];
__constant__ float c_tB[TSZ];

__device__ __forceinline__ void dfma(float2 &d, const float2 a, const float2 b) {
    asm("fma.rn.f32x2 %0, %1, %2, %0;"
        : "+l"(reinterpret_cast<unsigned long long &>(d))
        : "l"(reinterpret_cast<const unsigned long long &>(a)),
          "l"(reinterpret_cast<const unsigned long long &>(b)));
}

// ---------------------------------------------------------------- aux: denom + prep
// C entry ci (0..1053) <-> image col ci-15. Padded smem index: ci + (ci>>2).
__global__ __launch_bounds__(256)
void ncc_aux(const float* __restrict__ img, const float* __restrict__ t) {
    const int b = blockIdx.x;
    const int tid = threadIdx.x;

    if (b >= 192) {                       // ---- template prep (3 blocks, warp 0) ----
        if (tid >= 32) return;
        const int c = b - 192;
        const int lane = tid;
        const float* tc = t + c * 961;
        float s = 0.f;
        for (int i = lane; i < 961; i += 32) s += tc[i];
#pragma unroll
        for (int o = 16; o > 0; o >>= 1) s += __shfl_xor_sync(0xffffffffu, s, o);
        const float mu = s * INV961;
        float v = 0.f;
        for (int i = lane; i < 961; i += 32) { float d = tc[i] - mu; v = fmaf(d, d, v); }
#pragma unroll
        for (int o = 16; o > 0; o >>= 1) v += __shfl_xor_sync(0xffffffffu, v, o);
        const float sd = sqrtf(v * INV961);
        const float scale = 1.f / ((sd + EPSF) * 961.f);
        for (int idx = lane; idx < 31 * 32; idx += 32) {
            const int ri = idx >> 5, j = idx & 31;
            g_tA[c * 992 + idx] = (j < 31) ? (tc[ri * 31 + j] - mu) * scale : 0.f;
            g_tB[c * 992 + idx] = (j < 30) ? (tc[ri * 31 + j + 1] - mu) * scale : 0.f;
        }
        return;
    }

    // ---- streaming denominator ----
    __shared__ float C1[1320];
    __shared__ float C2[1320];
    const int pl = b >> 3, seg = b & 7;
    const int ry0 = seg << 7;
    const float* plane = img + ((size_t)pl << 20);

    for (int i = tid; i < 1320; i += 256) { C1[i] = 0.f; C2[i] = 0.f; }
    __syncthreads();

    for (int r = ry0 - 15; r <= ry0 + 15; ++r) {
        if ((unsigned)r >= 1024u) continue;
        const float* row = plane + ((size_t)r << 10);
        for (int ci = tid; ci < 1054; ci += 256) {
            const int col = ci - 15;
            if ((unsigned)col < 1024u) {
                const float v = row[col];
                const int pi = ci + (ci >> 2);
                C1[pi] += v;
                C2[pi] = fmaf(v, v, C2[pi]);
            }
        }
    }
    __syncthreads();

    const int x0 = tid << 2;
    float* Rseg = g_R + ((size_t)pl << 20) + x0;

#pragma unroll 1
    for (int y = ry0; y < ry0 + 128; ++y) {
        float S = 0.f, Q = 0.f, a0, a1, a2, b0, b1, b2;
#pragma unroll
        for (int j = 0; j < 31; ++j) {
            const int ci = x0 + j;
            const int pi = ci + (ci >> 2);
            const float c1v = C1[pi], c2v = C2[pi];
            S += c1v; Q += c2v;
            if (j == 0) { a0 = c1v; b0 = c2v; }
            if (j == 1) { a1 = c1v; b1 = c2v; }
            if (j == 2) { a2 = c1v; b2 = c2v; }
        }
        float n0, n1, n2, m0, m1v, m2v;
        {
            const int c31 = x0 + 31, c32 = x0 + 32, c33 = x0 + 33;
            n0 = C1[c31 + (c31 >> 2)]; m0  = C2[c31 + (c31 >> 2)];
            n1 = C1[c32 + (c32 >> 2)]; m1v = C2[c32 + (c32 >> 2)];
            n2 = C1[c33 + (c33 >> 2)]; m2v = C2[c33 + (c33 >> 2)];
        }
        const float s0 = S,            q0 = Q;
        const float s1 = s0 - a0 + n0, q1 = q0 - b0 + m0;
        const float s2 = s1 - a1 + n1, q2 = q1 - b1 + m1v;
        const float s3 = s2 - a2 + n2, q3 = q2 - b2 + m2v;

        float4 rv;
        { const float m = s0 * INV961; rv.x = 1.f / (sqrtf(fmaf(-m, m, q0 * INV961)) + EPSF); }
        { const float m = s1 * INV961; rv.y = 1.f / (sqrtf(fmaf(-m, m, q1 * INV961)) + EPSF); }
        { const float m = s2 * INV961; rv.z = 1.f / (sqrtf(fmaf(-m, m, q2 * INV961)) + EPSF); }
        { const float m = s3 * INV961; rv.w = 1.f / (sqrtf(fmaf(-m, m, q3 * INV961)) + EPSF); }
        *(float4*)(Rseg + ((size_t)y << 10)) = rv;

        __syncthreads();
        {
            const int ya = y + 16, ys = y - 15;
            const float* rowa = plane + ((size_t)ya << 10);
            const float* rows = plane + ((size_t)ys << 10);
            const bool va = (ya < 1024), vs = (ys >= 0);
            for (int ci = tid; ci < 1054; ci += 256) {
                const int col = ci - 15;
                if ((unsigned)col < 1024u) {
                    const float fa = va ? rowa[col] : 0.f;
                    const float fs = vs ? rows[col] : 0.f;
                    const int pi = ci + (ci >> 2);
                    C1[pi] += fa - fs;
                    C2[pi] += fa * fa - fs * fs;
                }
            }
        }
        __syncthreads();
    }
}

// ---------------------------------------------------------------- correlation row body
// Template rows come from __constant__ (LDC) at offsets toff0/toff1.
template<int DOP0, int DOP1>
__device__ __forceinline__ void corr_row2(
    const float* __restrict__ hrow, int toff0, int toff1,
    float2* __restrict__ acc0, float2* __restrict__ acc1)
{
    float4 W0 = *(const float4*)(hrow);
    float4 W1 = *(const float4*)(hrow + 4);
    const float w1s = W0.y, w3s = W0.w, w5s = W1.y, w7s = W1.w;
#pragma unroll
    for (int q = 0; q < 8; ++q) {
        const float4 W2 = *(const float4*)(hrow + 8 + (q << 2));
        const float2 P0 = make_float2(W0.x, W0.y), P1 = make_float2(W0.z, W0.w);
        const float2 P2 = make_float2(W1.x, W1.y), P3 = make_float2(W1.z, W1.w);
        const float2 P4 = make_float2(W2.x, W2.y), P5 = make_float2(W2.z, W2.w);
        if (DOP0) {
            const float4 ta = *(const float4*)(c_tA + toff0 + (q << 2));
            const float4 tb = *(const float4*)(c_tB + toff0 + (q << 2));
            const float2 A0 = make_float2(ta.x, ta.y), A1 = make_float2(ta.z, ta.w);
            const float2 B0 = make_float2(tb.x, tb.y), B1 = make_float2(tb.z, tb.w);
            dfma(acc0[0], P0, A0); dfma(acc0[2], P1, A0); dfma(acc0[4], P2, A0); dfma(acc0[6], P3, A0);
            dfma(acc0[1], P1, B0); dfma(acc0[3], P2, B0); dfma(acc0[5], P3, B0); dfma(acc0[7], P4, B0);
            dfma(acc0[0], P1, A1); dfma(acc0[2], P2, A1); dfma(acc0[4], P3, A1); dfma(acc0[6], P4, A1);
            dfma(acc0[1], P2, B1); dfma(acc0[3], P3, B1); dfma(acc0[5], P4, B1); dfma(acc0[7], P5, B1);
        }
        if (DOP1) {
            const float4 ta = *(const float4*)(c_tA + toff1 + (q << 2));
            const float4 tb = *(const float4*)(c_tB + toff1 + (q << 2));
            const float2 A0 = make_float2(ta.x, ta.y), A1 = make_float2(ta.z, ta.w);
            const float2 B0 = make_float2(tb.x, tb.y), B1 = make_float2(tb.z, tb.w);
            dfma(acc1[0], P0, A0); dfma(acc1[2], P1, A0); dfma(acc1[4], P2, A0); dfma(acc1[6], P3, A0);
            dfma(acc1[1], P1, B0); dfma(acc1[3], P2, B0); dfma(acc1[5], P3, B0); dfma(acc1[7], P4, B0);
            dfma(acc1[0], P1, A1); dfma(acc1[2], P2, A1); dfma(acc1[4], P3, A1); dfma(acc1[6], P4, A1);
            dfma(acc1[1], P2, B1); dfma(acc1[3], P3, B1); dfma(acc1[5], P4, B1); dfma(acc1[7], P5, B1);
        }
        W0 = W1; W1 = W2;
    }
    if (DOP0) {
        const float t0 = c_tA[toff0];   // tap(0) scalar for odd pixels (shifted template)
        acc0[1].x = fmaf(w1s, t0, acc0[1].x);
        acc0[3].x = fmaf(w3s, t0, acc0[3].x);
        acc0[5].x = fmaf(w5s, t0, acc0[5].x);
        acc0[7].x = fmaf(w7s, t0, acc0[7].x);
    }
    if (DOP1) {
        const float t0 = c_tA[toff1];
        acc1[1].x = fmaf(w1s, t0, acc1[1].x);
        acc1[3].x = fmaf(w3s, t0, acc1[3].x);
        acc1[5].x = fmaf(w5s, t0, acc1[5].x);
        acc1[7].x = fmaf(w7s, t0, acc1[7].x);
    }
}

// ---------------------------------------------------------------- main correlation
__global__ __launch_bounds__(128, 4)
void ncc_main(const float* __restrict__ img, float* __restrict__ out) {
    __shared__ __align__(16) float sh_halo[62][100];    // cols 0..95 valid, stride 100

    const int tx = threadIdx.x;           // 0..7
    const int ty = threadIdx.y;           // 0..15
    const int tid = ty * 8 + tx;
    const int bx = blockIdx.x, by = blockIdx.y, n = blockIdx.z;
    const int gx0 = bx << 6, gy0 = by << 5;
    const int x0 = tx << 3, y0 = ty << 1;  // 8 wide x 2 tall per thread

    float oacc[2][8];
#pragma unroll
    for (int p = 0; p < 2; ++p)
#pragma unroll
        for (int k = 0; k < 8; ++k) oacc[p][k] = 0.f;

    for (int c = 0; c < 3; ++c) {
        __syncthreads();
        // halo: 62 rows x 96 cols (zero outside image)
        if (tid < 96) {
            const float* plane = img + ((size_t)(n * 3 + c) << 20);
            const int gx = gx0 - 15 + tid;
            const bool xok = (unsigned)gx < 1024u;
#pragma unroll 1
            for (int r = 0; r < 62; ++r) {
                const int gy = gy0 - 15 + r;
                float v = 0.f;
                if (xok && ((unsigned)gy < 1024u)) v = plane[((size_t)gy << 10) + gx];
                sh_halo[r][tid] = v;
            }
        }
        __syncthreads();

        float2 acc0[8], acc1[8];
#pragma unroll
        for (int k = 0; k < 8; ++k) { acc0[k] = make_float2(0.f, 0.f); acc1[k] = make_float2(0.f, 0.f); }

        const int tc0 = c * 992;
        // r=0: only p=0 (template row 0); r=1..30: both; r=31: only p=1 (template row 30)
        corr_row2<1, 0>(&sh_halo[y0][x0], tc0, tc0, acc0, acc1);
#pragma unroll 1
        for (int r = 1; r < 31; ++r) {
            corr_row2<1, 1>(&sh_halo[y0 + r][x0],
                            tc0 + (r << 5), tc0 + ((r - 1) << 5), acc0, acc1);
        }
        corr_row2<0, 1>(&sh_halo[y0 + 31][x0], tc0, tc0 + (30 << 5), acc0, acc1);

        // combine with precomputed reciprocal denominator
        {
            const float* Rpl = g_R + ((size_t)(n * 3 + c) << 20);
            {
                const float* rp = Rpl + ((size_t)(gy0 + y0) << 10) + gx0 + x0;
                const float4 r0 = *(const float4*)rp;
                const float4 r1 = *(const float4*)(rp + 4);
                oacc[0][0] += (acc0[0].x + acc0[0].y) * r0.x;
                oacc[0][1] += (acc0[1].x + acc0[1].y) * r0.y;
                oacc[0][2] += (acc0[2].x + acc0[2].y) * r0.z;
                oacc[0][3] += (acc0[3].x + acc0[3].y) * r0.w;
                oacc[0][4] += (acc0[4].x + acc0[4].y) * r1.x;
                oacc[0][5] += (acc0[5].x + acc0[5].y) * r1.y;
                oacc[0][6] += (acc0[6].x + acc0[6].y) * r1.z;
                oacc[0][7] += (acc0[7].x + acc0[7].y) * r1.w;
            }
            {
                const float* rp = Rpl + ((size_t)(gy0 + y0 + 1) << 10) + gx0 + x0;
                const float4 r0 = *(const float4*)rp;
                const float4 r1 = *(const float4*)(rp + 4);
                oacc[1][0] += (acc1[0].x + acc1[0].y) * r0.x;
                oacc[1][1] += (acc1[1].x + acc1[1].y) * r0.y;
                oacc[1][2] += (acc1[2].x + acc1[2].y) * r0.z;
                oacc[1][3] += (acc1[3].x + acc1[3].y) * r0.w;
                oacc[1][4] += (acc1[4].x + acc1[4].y) * r1.x;
                oacc[1][5] += (acc1[5].x + acc1[5].y) * r1.y;
                oacc[1][6] += (acc1[6].x + acc1[6].y) * r1.z;
                oacc[1][7] += (acc1[7].x + acc1[7].y) * r1.w;
            }
        }
    }

    // write out: mean over channels, NaN -> 0
#pragma unroll
    for (int p = 0; p < 2; ++p) {
        float v[8];
#pragma unroll
        for (int k = 0; k < 8; ++k) {
            const float r = oacc[p][k] * (1.0f / 3.0f);
            v[k] = (r == r) ? r : 0.f;
        }
        float* dst = out + (((size_t)n << 20) + ((size_t)(gy0 + y0 + p) << 10) + gx0 + x0);
        *(float4*)dst       = make_float4(v[0], v[1], v[2], v[3]);
        *(float4*)(dst + 4) = make_float4(v[4], v[5], v[6], v[7]);
    }
}

extern "C" void kernel_launch(void* const* d_in, const int* in_sizes, int n_in,
                              void* d_out, int out_size) {
    (void)in_sizes; (void)n_in; (void)out_size;
    const float* img  = (const float*)d_in[0];
    const float* tmpl = (const float*)d_in[1];
    float* out = (float*)d_out;

    ncc_aux<<<195, 256>>>(img, tmpl);                       // denom (192) + prep (3)

    // copy normalized template into constant memory (graph-legal async D2D)
    void *pA = nullptr, *pB = nullptr, *gA = nullptr, *gB = nullptr;
    cudaGetSymbolAddress(&pA, c_tA);
    cudaGetSymbolAddress(&pB, c_tB);
    cudaGetSymbolAddress(&gA, g_tA);
    cudaGetSymbolAddress(&gB, g_tB);
    cudaMemcpyAsync(pA, gA, TSZ * sizeof(float), cudaMemcpyDeviceToDevice);
    cudaMemcpyAsync(pB, gB, TSZ * sizeof(float), cudaMemcpyDeviceToDevice);

    ncc_main<<<dim3(16, 32, 8), dim3(8, 16)>>>(img, out);
}

// round 12
// speedup vs baseline: 1.3392x; 1.0183x over previous
#include <cuda_runtime.h>

// NCC: image (8,3,1024,1024) f32, template (3,31,31) f32, stride 1, pad 15.
// out (8,1024,1024) f32 = mean_c[ conv(img, norm_t) / (sqrt(m2-m1^2)+eps) ], NaN->0
//
// R12 = R11 resubmitted verbatim (R11 never ran: broker container failure).
//   ncc_aux  : 768 blocks (32-row segments) streaming denominator -> g_R ;
//              3 blocks template prep -> g_tA (rows padded to 36 floats, taps 31..35 = 0)
//   (memcpy) : g_tA -> __constant__ c_tA
//   ncc_main : correlation, all fma.rn.f32x2. Single template copy; odd-pixel shifted
//              pairs built in registers (MOVs on alu pipe) from a sliding template
//              window -> 18 LDC.128/row instead of 32 (const-port floor no longer binding).

#define EPSF 1e-9f
#define INV961 (1.0f/961.0f)
#define PLANE_ELEMS (24*1024*1024)
#define TROW 36                      // padded template row stride (floats)
#define TCH  (31*TROW)               // per-channel template floats (1116)
#define TSZ  (3*TCH)                 // 3348

__device__ float g_tA[TSZ];
__device__ float g_R [PLANE_ELEMS];

__constant__ float c_tA[TSZ];

__device__ __forceinline__ void dfma(float2 &d, const float2 a, const float2 b) {
    asm("fma.rn.f32x2 %0, %1, %2, %0;"
        : "+l"(reinterpret_cast<unsigned long long &>(d))
        : "l"(reinterpret_cast<const unsigned long long &>(a)),
          "l"(reinterpret_cast<const unsigned long long &>(b)));
}

// ---------------------------------------------------------------- aux: denom + prep
// C entry ci (0..1053) <-> image col ci-15. Padded smem index: ci + (ci>>2).
__global__ __launch_bounds__(256)
void ncc_aux(const float* __restrict__ img, const float* __restrict__ t) {
    const int b = blockIdx.x;
    const int tid = threadIdx.x;

    if (b >= 768) {                       // ---- template prep (3 blocks, warp 0) ----
        if (tid >= 32) return;
        const int c = b - 768;
        const int lane = tid;
        const float* tc = t + c * 961;
        float s = 0.f;
        for (int i = lane; i < 961; i += 32) s += tc[i];
#pragma unroll
        for (int o = 16; o > 0; o >>= 1) s += __shfl_xor_sync(0xffffffffu, s, o);
        const float mu = s * INV961;
        float v = 0.f;
        for (int i = lane; i < 961; i += 32) { float d = tc[i] - mu; v = fmaf(d, d, v); }
#pragma unroll
        for (int o = 16; o > 0; o >>= 1) v += __shfl_xor_sync(0xffffffffu, v, o);
        const float sd = sqrtf(v * INV961);
        const float scale = 1.f / ((sd + EPSF) * 961.f);
        for (int idx = lane; idx < TCH; idx += 32) {
            const int ri = idx / TROW, j = idx % TROW;
            g_tA[c * TCH + idx] = (j < 31) ? (tc[ri * 31 + j] - mu) * scale : 0.f;
        }
        return;
    }

    // ---- streaming denominator: one plane x 32-row segment per block ----
    __shared__ float C1[1320];
    __shared__ float C2[1320];
    const int pl = b >> 5, seg = b & 31;
    const int ry0 = seg << 5;
    const float* plane = img + ((size_t)pl << 20);

    for (int i = tid; i < 1320; i += 256) { C1[i] = 0.f; C2[i] = 0.f; }
    __syncthreads();

    for (int r = ry0 - 15; r <= ry0 + 15; ++r) {
        if ((unsigned)r >= 1024u) continue;
        const float* row = plane + ((size_t)r << 10);
        for (int ci = tid; ci < 1054; ci += 256) {
            const int col = ci - 15;
            if ((unsigned)col < 1024u) {
                const float v = row[col];
                const int pi = ci + (ci >> 2);
                C1[pi] += v;
                C2[pi] = fmaf(v, v, C2[pi]);
            }
        }
    }
    __syncthreads();

    const int x0 = tid << 2;
    float* Rseg = g_R + ((size_t)pl << 20) + x0;

#pragma unroll 1
    for (int y = ry0; y < ry0 + 32; ++y) {
        float S = 0.f, Q = 0.f, a0, a1, a2, b0, b1, b2;
#pragma unroll
        for (int j = 0; j < 31; ++j) {
            const int ci = x0 + j;
            const int pi = ci + (ci >> 2);
            const float c1v = C1[pi], c2v = C2[pi];
            S += c1v; Q += c2v;
            if (j == 0) { a0 = c1v; b0 = c2v; }
            if (j == 1) { a1 = c1v; b1 = c2v; }
            if (j == 2) { a2 = c1v; b2 = c2v; }
        }
        float n0, n1, n2, m0, m1v, m2v;
        {
            const int c31 = x0 + 31, c32 = x0 + 32, c33 = x0 + 33;
            n0 = C1[c31 + (c31 >> 2)]; m0  = C2[c31 + (c31 >> 2)];
            n1 = C1[c32 + (c32 >> 2)]; m1v = C2[c32 + (c32 >> 2)];
            n2 = C1[c33 + (c33 >> 2)]; m2v = C2[c33 + (c33 >> 2)];
        }
        const float s0 = S,            q0 = Q;
        const float s1 = s0 - a0 + n0, q1 = q0 - b0 + m0;
        const float s2 = s1 - a1 + n1, q2 = q1 - b1 + m1v;
        const float s3 = s2 - a2 + n2, q3 = q2 - b2 + m2v;

        float4 rv;
        { const float m = s0 * INV961; rv.x = 1.f / (sqrtf(fmaf(-m, m, q0 * INV961)) + EPSF); }
        { const float m = s1 * INV961; rv.y = 1.f / (sqrtf(fmaf(-m, m, q1 * INV961)) + EPSF); }
        { const float m = s2 * INV961; rv.z = 1.f / (sqrtf(fmaf(-m, m, q2 * INV961)) + EPSF); }
        { const float m = s3 * INV961; rv.w = 1.f / (sqrtf(fmaf(-m, m, q3 * INV961)) + EPSF); }
        *(float4*)(Rseg + ((size_t)y << 10)) = rv;

        __syncthreads();
        {
            const int ya = y + 16, ys = y - 15;
            const float* rowa = plane + ((size_t)ya << 10);
            const float* rows = plane + ((size_t)ys << 10);
            const bool va = (ya < 1024), vs = (ys >= 0);
            for (int ci = tid; ci < 1054; ci += 256) {
                const int col = ci - 15;
                if ((unsigned)col < 1024u) {
                    const float fa = va ? rowa[col] : 0.f;
                    const float fs = vs ? rows[col] : 0.f;
                    const int pi = ci + (ci >> 2);
                    C1[pi] += fa - fs;
                    C2[pi] += fa * fa - fs * fs;
                }
            }
        }
        __syncthreads();
    }
}

// ---------------------------------------------------------------- correlation row body
// Single template copy (c_tA, stride-36 rows, taps 31..35 zero).
// Odd-pixel pairs B0=(t1,t2), B1=(t3,t4) built in registers from sliding window.
template<int DOP0, int DOP1>
__device__ __forceinline__ void corr_row2(
    const float* __restrict__ hrow, int toff0, int toff1,
    float2* __restrict__ acc0, float2* __restrict__ acc1)
{
    float4 W0 = *(const float4*)(hrow);
    float4 W1 = *(const float4*)(hrow + 4);
    const float w1s = W0.y, w3s = W0.w, w5s = W1.y, w7s = W1.w;
    float4 Ta0, Ta1;
    float t00 = 0.f, t01 = 0.f;
    if (DOP0) { Ta0 = *(const float4*)(c_tA + toff0); t00 = Ta0.x; }
    if (DOP1) { Ta1 = *(const float4*)(c_tA + toff1); t01 = Ta1.x; }
#pragma unroll
    for (int q = 0; q < 8; ++q) {
        const float4 W2 = *(const float4*)(hrow + 8 + (q << 2));
        const float2 P0 = make_float2(W0.x, W0.y), P1 = make_float2(W0.z, W0.w);
        const float2 P2 = make_float2(W1.x, W1.y), P3 = make_float2(W1.z, W1.w);
        const float2 P4 = make_float2(W2.x, W2.y), P5 = make_float2(W2.z, W2.w);
        if (DOP0) {
            const float4 Tn = *(const float4*)(c_tA + toff0 + ((q + 1) << 2));
            const float2 A0 = make_float2(Ta0.x, Ta0.y), A1 = make_float2(Ta0.z, Ta0.w);
            const float2 B0 = make_float2(Ta0.y, Ta0.z), B1 = make_float2(Ta0.w, Tn.x);
            dfma(acc0[0], P0, A0); dfma(acc0[2], P1, A0); dfma(acc0[4], P2, A0); dfma(acc0[6], P3, A0);
            dfma(acc0[1], P1, B0); dfma(acc0[3], P2, B0); dfma(acc0[5], P3, B0); dfma(acc0[7], P4, B0);
            dfma(acc0[0], P1, A1); dfma(acc0[2], P2, A1); dfma(acc0[4], P3, A1); dfma(acc0[6], P4, A1);
            dfma(acc0[1], P2, B1); dfma(acc0[3], P3, B1); dfma(acc0[5], P4, B1); dfma(acc0[7], P5, B1);
            Ta0 = Tn;
        }
        if (DOP1) {
            const float4 Tn = *(const float4*)(c_tA + toff1 + ((q + 1) << 2));
            const float2 A0 = make_float2(Ta1.x, Ta1.y), A1 = make_float2(Ta1.z, Ta1.w);
            const float2 B0 = make_float2(Ta1.y, Ta1.z), B1 = make_float2(Ta1.w, Tn.x);
            dfma(acc1[0], P0, A0); dfma(acc1[2], P1, A0); dfma(acc1[4], P2, A0); dfma(acc1[6], P3, A0);
            dfma(acc1[1], P1, B0); dfma(acc1[3], P2, B0); dfma(acc1[5], P3, B0); dfma(acc1[7], P4, B0);
            dfma(acc1[0], P1, A1); dfma(acc1[2], P2, A1); dfma(acc1[4], P3, A1); dfma(acc1[6], P4, A1);
            dfma(acc1[1], P2, B1); dfma(acc1[3], P3, B1); dfma(acc1[5], P4, B1); dfma(acc1[7], P5, B1);
            Ta1 = Tn;
        }
        W0 = W1; W1 = W2;
    }
    if (DOP0) {     // odd pixels' missing tap-0 term
        acc0[1].x = fmaf(w1s, t00, acc0[1].x);
        acc0[3].x = fmaf(w3s, t00, acc0[3].x);
        acc0[5].x = fmaf(w5s, t00, acc0[5].x);
        acc0[7].x = fmaf(w7s, t00, acc0[7].x);
    }
    if (DOP1) {
        acc1[1].x = fmaf(w1s, t01, acc1[1].x);
        acc1[3].x = fmaf(w3s, t01, acc1[3].x);
        acc1[5].x = fmaf(w5s, t01, acc1[5].x);
        acc1[7].x = fmaf(w7s, t01, acc1[7].x);
    }
}

// ---------------------------------------------------------------- main correlation
__global__ __launch_bounds__(128, 4)
void ncc_main(const float* __restrict__ img, float* __restrict__ out) {
    __shared__ __align__(16) float sh_halo[62][100];    // cols 0..95 valid, stride 100

    const int tx = threadIdx.x;           // 0..7
    const int ty = threadIdx.y;           // 0..15
    const int tid = ty * 8 + tx;
    const int bx = blockIdx.x, by = blockIdx.y, n = blockIdx.z;
    const int gx0 = bx << 6, gy0 = by << 5;
    const int x0 = tx << 3, y0 = ty << 1;  // 8 wide x 2 tall per thread

    float oacc[2][8];
#pragma unroll
    for (int p = 0; p < 2; ++p)
#pragma unroll
        for (int k = 0; k < 8; ++k) oacc[p][k] = 0.f;

    for (int c = 0; c < 3; ++c) {
        __syncthreads();
        // halo: 62 rows x 96 cols (zero outside image)
        if (tid < 96) {
            const float* plane = img + ((size_t)(n * 3 + c) << 20);
            const int gx = gx0 - 15 + tid;
            const bool xok = (unsigned)gx < 1024u;
#pragma unroll 1
            for (int r = 0; r < 62; ++r) {
                const int gy = gy0 - 15 + r;
                float v = 0.f;
                if (xok && ((unsigned)gy < 1024u)) v = plane[((size_t)gy << 10) + gx];
                sh_halo[r][tid] = v;
            }
        }
        __syncthreads();

        float2 acc0[8], acc1[8];
#pragma unroll
        for (int k = 0; k < 8; ++k) { acc0[k] = make_float2(0.f, 0.f); acc1[k] = make_float2(0.f, 0.f); }

        const int tc0 = c * TCH;
        // r=0: only p=0 (template row 0); r=1..30: both; r=31: only p=1 (template row 30)
        corr_row2<1, 0>(&sh_halo[y0][x0], tc0, tc0, acc0, acc1);
#pragma unroll 1
        for (int r = 1; r < 31; ++r) {
            corr_row2<1, 1>(&sh_halo[y0 + r][x0],
                            tc0 + r * TROW, tc0 + (r - 1) * TROW, acc0, acc1);
        }
        corr_row2<0, 1>(&sh_halo[y0 + 31][x0], tc0, tc0 + 30 * TROW, acc0, acc1);

        // combine with precomputed reciprocal denominator
        {
            const float* Rpl = g_R + ((size_t)(n * 3 + c) << 20);
            {
                const float* rp = Rpl + ((size_t)(gy0 + y0) << 10) + gx0 + x0;
                const float4 r0 = *(const float4*)rp;
                const float4 r1 = *(const float4*)(rp + 4);
                oacc[0][0] += (acc0[0].x + acc0[0].y) * r0.x;
                oacc[0][1] += (acc0[1].x + acc0[1].y) * r0.y;
                oacc[0][2] += (acc0[2].x + acc0[2].y) * r0.z;
                oacc[0][3] += (acc0[3].x + acc0[3].y) * r0.w;
                oacc[0][4] += (acc0[4].x + acc0[4].y) * r1.x;
                oacc[0][5] += (acc0[5].x + acc0[5].y) * r1.y;
                oacc[0][6] += (acc0[6].x + acc0[6].y) * r1.z;
                oacc[0][7] += (acc0[7].x + acc0[7].y) * r1.w;
            }
            {
                const float* rp = Rpl + ((size_t)(gy0 + y0 + 1) << 10) + gx0 + x0;
                const float4 r0 = *(const float4*)rp;
                const float4 r1 = *(const float4*)(rp + 4);
                oacc[1][0] += (acc1[0].x + acc1[0].y) * r0.x;
                oacc[1][1] += (acc1[1].x + acc1[1].y) * r0.y;
                oacc[1][2] += (acc1[2].x + acc1[2].y) * r0.z;
                oacc[1][3] += (acc1[3].x + acc1[3].y) * r0.w;
                oacc[1][4] += (acc1[4].x + acc1[4].y) * r1.x;
                oacc[1][5] += (acc1[5].x + acc1[5].y) * r1.y;
                oacc[1][6] += (acc1[6].x + acc1[6].y) * r1.z;
                oacc[1][7] += (acc1[7].x + acc1[7].y) * r1.w;
            }
        }
    }

    // write out: mean over channels, NaN -> 0
#pragma unroll
    for (int p = 0; p < 2; ++p) {
        float v[8];
#pragma unroll
        for (int k = 0; k < 8; ++k) {
            const float r = oacc[p][k] * (1.0f / 3.0f);
            v[k] = (r == r) ? r : 0.f;
        }
        float* dst = out + (((size_t)n << 20) + ((size_t)(gy0 + y0 + p) << 10) + gx0 + x0);
        *(float4*)dst       = make_float4(v[0], v[1], v[2], v[3]);
        *(float4*)(dst + 4) = make_float4(v[4], v[5], v[6], v[7]);
    }
}

extern "C" void kernel_launch(void* const* d_in, const int* in_sizes, int n_in,
                              void* d_out, int out_size) {
    (void)in_sizes; (void)n_in; (void)out_size;
    const float* img  = (const float*)d_in[0];
    const float* tmpl = (const float*)d_in[1];
    float* out = (float*)d_out;

    ncc_aux<<<771, 256>>>(img, tmpl);                       // denom (768) + prep (3)

    // copy normalized template into constant memory (graph-legal async D2D)
    void *pA = nullptr, *gA = nullptr;
    cudaGetSymbolAddress(&pA, c_tA);
    cudaGetSymbolAddress(&gA, g_tA);
    cudaMemcpyAsync(pA, gA, TSZ * sizeof(float), cudaMemcpyDeviceToDevice);

    ncc_main<<<dim3(16, 32, 8), dim3(8, 16)>>>(img, out);
}

// round 13
// speedup vs baseline: 1.5756x; 1.1765x over previous
#include <cuda_runtime.h>

// NCC: image (8,3,1024,1024) f32, template (3,31,31) f32, stride 1, pad 15.
// out (8,1024,1024) f32 = mean_c[ conv(img, norm_t) / (sqrt(m2-m1^2)+eps) ], NaN->0
//
// R13 = best measured halves: R10's main (dual __constant__ template copies,
// main=1189us) + R12's aux (32-row-segment streaming denominator, aux=165us).
//   ncc_aux  : 768 blocks (32-row segments) streaming denominator -> g_R ;
//              3 blocks template prep -> g_tA (aligned) + g_tB (shift-1), stride 32
//   (memcpy) : g_tA/g_tB -> __constant__ c_tA/c_tB
//   ncc_main : correlation, all fma.rn.f32x2; image rows via sliding 3-float4 smem
//              window, template rows via LDC. 64x32 tile, 8x2 px/thread, (128,4).

#define EPSF 1e-9f
#define INV961 (1.0f/961.0f)
#define PLANE_ELEMS (24*1024*1024)
#define TSZ (3*31*32)

__device__ float g_tA[TSZ];
__device__ float g_tB[TSZ];
__device__ float g_R [PLANE_ELEMS];

__constant__ float c_tA[TSZ];
__constant__ float c_tB[TSZ];

__device__ __forceinline__ void dfma(float2 &d, const float2 a, const float2 b) {
    asm("fma.rn.f32x2 %0, %1, %2, %0;"
        : "+l"(reinterpret_cast<unsigned long long &>(d))
        : "l"(reinterpret_cast<const unsigned long long &>(a)),
          "l"(reinterpret_cast<const unsigned long long &>(b)));
}

// ---------------------------------------------------------------- aux: denom + prep
// C entry ci (0..1053) <-> image col ci-15. Padded smem index: ci + (ci>>2).
__global__ __launch_bounds__(256)
void ncc_aux(const float* __restrict__ img, const float* __restrict__ t) {
    const int b = blockIdx.x;
    const int tid = threadIdx.x;

    if (b >= 768) {                       // ---- template prep (3 blocks, warp 0) ----
        if (tid >= 32) return;
        const int c = b - 768;
        const int lane = tid;
        const float* tc = t + c * 961;
        float s = 0.f;
        for (int i = lane; i < 961; i += 32) s += tc[i];
#pragma unroll
        for (int o = 16; o > 0; o >>= 1) s += __shfl_xor_sync(0xffffffffu, s, o);
        const float mu = s * INV961;
        float v = 0.f;
        for (int i = lane; i < 961; i += 32) { float d = tc[i] - mu; v = fmaf(d, d, v); }
#pragma unroll
        for (int o = 16; o > 0; o >>= 1) v += __shfl_xor_sync(0xffffffffu, v, o);
        const float sd = sqrtf(v * INV961);
        const float scale = 1.f / ((sd + EPSF) * 961.f);
        for (int idx = lane; idx < 31 * 32; idx += 32) {
            const int ri = idx >> 5, j = idx & 31;
            g_tA[c * 992 + idx] = (j < 31) ? (tc[ri * 31 + j] - mu) * scale : 0.f;
            g_tB[c * 992 + idx] = (j < 30) ? (tc[ri * 31 + j + 1] - mu) * scale : 0.f;
        }
        return;
    }

    // ---- streaming denominator: one plane x 32-row segment per block ----
    __shared__ float C1[1320];
    __shared__ float C2[1320];
    const int pl = b >> 5, seg = b & 31;
    const int ry0 = seg << 5;
    const float* plane = img + ((size_t)pl << 20);

    for (int i = tid; i < 1320; i += 256) { C1[i] = 0.f; C2[i] = 0.f; }
    __syncthreads();

    for (int r = ry0 - 15; r <= ry0 + 15; ++r) {
        if ((unsigned)r >= 1024u) continue;
        const float* row = plane + ((size_t)r << 10);
        for (int ci = tid; ci < 1054; ci += 256) {
            const int col = ci - 15;
            if ((unsigned)col < 1024u) {
                const float v = row[col];
                const int pi = ci + (ci >> 2);
                C1[pi] += v;
                C2[pi] = fmaf(v, v, C2[pi]);
            }
        }
    }
    __syncthreads();

    const int x0 = tid << 2;
    float* Rseg = g_R + ((size_t)pl << 20) + x0;

#pragma unroll 1
    for (int y = ry0; y < ry0 + 32; ++y) {
        float S = 0.f, Q = 0.f, a0, a1, a2, b0, b1, b2;
#pragma unroll
        for (int j = 0; j < 31; ++j) {
            const int ci = x0 + j;
            const int pi = ci + (ci >> 2);
            const float c1v = C1[pi], c2v = C2[pi];
            S += c1v; Q += c2v;
            if (j == 0) { a0 = c1v; b0 = c2v; }
            if (j == 1) { a1 = c1v; b1 = c2v; }
            if (j == 2) { a2 = c1v; b2 = c2v; }
        }
        float n0, n1, n2, m0, m1v, m2v;
        {
            const int c31 = x0 + 31, c32 = x0 + 32, c33 = x0 + 33;
            n0 = C1[c31 + (c31 >> 2)]; m0  = C2[c31 + (c31 >> 2)];
            n1 = C1[c32 + (c32 >> 2)]; m1v = C2[c32 + (c32 >> 2)];
            n2 = C1[c33 + (c33 >> 2)]; m2v = C2[c33 + (c33 >> 2)];
        }
        const float s0 = S,            q0 = Q;
        const float s1 = s0 - a0 + n0, q1 = q0 - b0 + m0;
        const float s2 = s1 - a1 + n1, q2 = q1 - b1 + m1v;
        const float s3 = s2 - a2 + n2, q3 = q2 - b2 + m2v;

        float4 rv;
        { const float m = s0 * INV961; rv.x = 1.f / (sqrtf(fmaf(-m, m, q0 * INV961)) + EPSF); }
        { const float m = s1 * INV961; rv.y = 1.f / (sqrtf(fmaf(-m, m, q1 * INV961)) + EPSF); }
        { const float m = s2 * INV961; rv.z = 1.f / (sqrtf(fmaf(-m, m, q2 * INV961)) + EPSF); }
        { const float m = s3 * INV961; rv.w = 1.f / (sqrtf(fmaf(-m, m, q3 * INV961)) + EPSF); }
        *(float4*)(Rseg + ((size_t)y << 10)) = rv;

        __syncthreads();
        {
            const int ya = y + 16, ys = y - 15;
            const float* rowa = plane + ((size_t)ya << 10);
            const float* rows = plane + ((size_t)ys << 10);
            const bool va = (ya < 1024), vs = (ys >= 0);
            for (int ci = tid; ci < 1054; ci += 256) {
                const int col = ci - 15;
                if ((unsigned)col < 1024u) {
                    const float fa = va ? rowa[col] : 0.f;
                    const float fs = vs ? rows[col] : 0.f;
                    const int pi = ci + (ci >> 2);
                    C1[pi] += fa - fs;
                    C2[pi] += fa * fa - fs * fs;
                }
            }
        }
        __syncthreads();
    }
}

// ---------------------------------------------------------------- correlation row body
// Template rows come from __constant__ (LDC) at offsets toff0/toff1 (dual copies).
template<int DOP0, int DOP1>
__device__ __forceinline__ void corr_row2(
    const float* __restrict__ hrow, int toff0, int toff1,
    float2* __restrict__ acc0, float2* __restrict__ acc1)
{
    float4 W0 = *(const float4*)(hrow);
    float4 W1 = *(const float4*)(hrow + 4);
    const float w1s = W0.y, w3s = W0.w, w5s = W1.y, w7s = W1.w;
#pragma unroll
    for (int q = 0; q < 8; ++q) {
        const float4 W2 = *(const float4*)(hrow + 8 + (q << 2));
        const float2 P0 = make_float2(W0.x, W0.y), P1 = make_float2(W0.z, W0.w);
        const float2 P2 = make_float2(W1.x, W1.y), P3 = make_float2(W1.z, W1.w);
        const float2 P4 = make_float2(W2.x, W2.y), P5 = make_float2(W2.z, W2.w);
        if (DOP0) {
            const float4 ta = *(const float4*)(c_tA + toff0 + (q << 2));
            const float4 tb = *(const float4*)(c_tB + toff0 + (q << 2));
            const float2 A0 = make_float2(ta.x, ta.y), A1 = make_float2(ta.z, ta.w);
            const float2 B0 = make_float2(tb.x, tb.y), B1 = make_float2(tb.z, tb.w);
            dfma(acc0[0], P0, A0); dfma(acc0[2], P1, A0); dfma(acc0[4], P2, A0); dfma(acc0[6], P3, A0);
            dfma(acc0[1], P1, B0); dfma(acc0[3], P2, B0); dfma(acc0[5], P3, B0); dfma(acc0[7], P4, B0);
            dfma(acc0[0], P1, A1); dfma(acc0[2], P2, A1); dfma(acc0[4], P3, A1); dfma(acc0[6], P4, A1);
            dfma(acc0[1], P2, B1); dfma(acc0[3], P3, B1); dfma(acc0[5], P4, B1); dfma(acc0[7], P5, B1);
        }
        if (DOP1) {
            const float4 ta = *(const float4*)(c_tA + toff1 + (q << 2));
            const float4 tb = *(const float4*)(c_tB + toff1 + (q << 2));
            const float2 A0 = make_float2(ta.x, ta.y), A1 = make_float2(ta.z, ta.w);
            const float2 B0 = make_float2(tb.x, tb.y), B1 = make_float2(tb.z, tb.w);
            dfma(acc1[0], P0, A0); dfma(acc1[2], P1, A0); dfma(acc1[4], P2, A0); dfma(acc1[6], P3, A0);
            dfma(acc1[1], P1, B0); dfma(acc1[3], P2, B0); dfma(acc1[5], P3, B0); dfma(acc1[7], P4, B0);
            dfma(acc1[0], P1, A1); dfma(acc1[2], P2, A1); dfma(acc1[4], P3, A1); dfma(acc1[6], P4, A1);
            dfma(acc1[1], P2, B1); dfma(acc1[3], P3, B1); dfma(acc1[5], P4, B1); dfma(acc1[7], P5, B1);
        }
        W0 = W1; W1 = W2;
    }
    if (DOP0) {
        const float t0 = c_tA[toff0];   // tap(0) scalar for odd pixels (shifted template)
        acc0[1].x = fmaf(w1s, t0, acc0[1].x);
        acc0[3].x = fmaf(w3s, t0, acc0[3].x);
        acc0[5].x = fmaf(w5s, t0, acc0[5].x);
        acc0[7].x = fmaf(w7s, t0, acc0[7].x);
    }
    if (DOP1) {
        const float t0 = c_tA[toff1];
        acc1[1].x = fmaf(w1s, t0, acc1[1].x);
        acc1[3].x = fmaf(w3s, t0, acc1[3].x);
        acc1[5].x = fmaf(w5s, t0, acc1[5].x);
        acc1[7].x = fmaf(w7s, t0, acc1[7].x);
    }
}

// ---------------------------------------------------------------- main correlation
__global__ __launch_bounds__(128, 4)
void ncc_main(const float* __restrict__ img, float* __restrict__ out) {
    __shared__ __align__(16) float sh_halo[62][100];    // cols 0..95 valid, stride 100

    const int tx = threadIdx.x;           // 0..7
    const int ty = threadIdx.y;           // 0..15
    const int tid = ty * 8 + tx;
    const int bx = blockIdx.x, by = blockIdx.y, n = blockIdx.z;
    const int gx0 = bx << 6, gy0 = by << 5;
    const int x0 = tx << 3, y0 = ty << 1;  // 8 wide x 2 tall per thread

    float oacc[2][8];
#pragma unroll
    for (int p = 0; p < 2; ++p)
#pragma unroll
        for (int k = 0; k < 8; ++k) oacc[p][k] = 0.f;

    for (int c = 0; c < 3; ++c) {
        __syncthreads();
        // halo: 62 rows x 96 cols (zero outside image)
        if (tid < 96) {
            const float* plane = img + ((size_t)(n * 3 + c) << 20);
            const int gx = gx0 - 15 + tid;
            const bool xok = (unsigned)gx < 1024u;
#pragma unroll 1
            for (int r = 0; r < 62; ++r) {
                const int gy = gy0 - 15 + r;
                float v = 0.f;
                if (xok && ((unsigned)gy < 1024u)) v = plane[((size_t)gy << 10) + gx];
                sh_halo[r][tid] = v;
            }
        }
        __syncthreads();

        float2 acc0[8], acc1[8];
#pragma unroll
        for (int k = 0; k < 8; ++k) { acc0[k] = make_float2(0.f, 0.f); acc1[k] = make_float2(0.f, 0.f); }

        const int tc0 = c * 992;
        // r=0: only p=0 (template row 0); r=1..30: both; r=31: only p=1 (template row 30)
        corr_row2<1, 0>(&sh_halo[y0][x0], tc0, tc0, acc0, acc1);
#pragma unroll 1
        for (int r = 1; r < 31; ++r) {
            corr_row2<1, 1>(&sh_halo[y0 + r][x0],
                            tc0 + (r << 5), tc0 + ((r - 1) << 5), acc0, acc1);
        }
        corr_row2<0, 1>(&sh_halo[y0 + 31][x0], tc0, tc0 + (30 << 5), acc0, acc1);

        // combine with precomputed reciprocal denominator
        {
            const float* Rpl = g_R + ((size_t)(n * 3 + c) << 20);
            {
                const float* rp = Rpl + ((size_t)(gy0 + y0) << 10) + gx0 + x0;
                const float4 r0 = *(const float4*)rp;
                const float4 r1 = *(const float4*)(rp + 4);
                oacc[0][0] += (acc0[0].x + acc0[0].y) * r0.x;
                oacc[0][1] += (acc0[1].x + acc0[1].y) * r0.y;
                oacc[0][2] += (acc0[2].x + acc0[2].y) * r0.z;
                oacc[0][3] += (acc0[3].x + acc0[3].y) * r0.w;
                oacc[0][4] += (acc0[4].x + acc0[4].y) * r1.x;
                oacc[0][5] += (acc0[5].x + acc0[5].y) * r1.y;
                oacc[0][6] += (acc0[6].x + acc0[6].y) * r1.z;
                oacc[0][7] += (acc0[7].x + acc0[7].y) * r1.w;
            }
            {
                const float* rp = Rpl + ((size_t)(gy0 + y0 + 1) << 10) + gx0 + x0;
                const float4 r0 = *(const float4*)rp;
                const float4 r1 = *(const float4*)(rp + 4);
                oacc[1][0] += (acc1[0].x + acc1[0].y) * r0.x;
                oacc[1][1] += (acc1[1].x + acc1[1].y) * r0.y;
                oacc[1][2] += (acc1[2].x + acc1[2].y) * r0.z;
                oacc[1][3] += (acc1[3].x + acc1[3].y) * r0.w;
                oacc[1][4] += (acc1[4].x + acc1[4].y) * r1.x;
                oacc[1][5] += (acc1[5].x + acc1[5].y) * r1.y;
                oacc[1][6] += (acc1[6].x + acc1[6].y) * r1.z;
                oacc[1][7] += (acc1[7].x + acc1[7].y) * r1.w;
            }
        }
    }

    // write out: mean over channels, NaN -> 0
#pragma unroll
    for (int p = 0; p < 2; ++p) {
        float v[8];
#pragma unroll
        for (int k = 0; k < 8; ++k) {
            const float r = oacc[p][k] * (1.0f / 3.0f);
            v[k] = (r == r) ? r : 0.f;
        }
        float* dst = out + (((size_t)n << 20) + ((size_t)(gy0 + y0 + p) << 10) + gx0 + x0);
        *(float4*)dst       = make_float4(v[0], v[1], v[2], v[3]);
        *(float4*)(dst + 4) = make_float4(v[4], v[5], v[6], v[7]);
    }
}

extern "C" void kernel_launch(void* const* d_in, const int* in_sizes, int n_in,
                              void* d_out, int out_size) {
    (void)in_sizes; (void)n_in; (void)out_size;
    const float* img  = (const float*)d_in[0];
    const float* tmpl = (const float*)d_in[1];
    float* out = (float*)d_out;

    ncc_aux<<<771, 256>>>(img, tmpl);                       // denom (768) + prep (3)

    // copy normalized template into constant memory (graph-legal async D2D)
    void *pA = nullptr, *pB = nullptr, *gA = nullptr, *gB = nullptr;
    cudaGetSymbolAddress(&pA, c_tA);
    cudaGetSymbolAddress(&pB, c_tB);
    cudaGetSymbolAddress(&gA, g_tA);
    cudaGetSymbolAddress(&gB, g_tB);
    cudaMemcpyAsync(pA, gA, TSZ * sizeof(float), cudaMemcpyDeviceToDevice);
    cudaMemcpyAsync(pB, gB, TSZ * sizeof(float), cudaMemcpyDeviceToDevice);

    ncc_main<<<dim3(16, 32, 8), dim3(8, 16)>>>(img, out);
}

// round 14
// speedup vs baseline: 1.6425x; 1.0425x over previous
#include <cuda_runtime.h>

// NCC: image (8,3,1024,1024) f32, template (3,31,31) f32, stride 1, pad 15.
// out (8,1024,1024) f32 = mean_c[ conv(img, norm_t) / (sqrt(m2-m1^2)+eps) ], NaN->0
//
// R14 = R13 + oacc moved to thread-private smem columns, freeing 16 regs so
// __launch_bounds__(128,5) yields 5 blocks/SM = 20 warps (5/SMSP, was 4).
//   ncc_aux  : 768 blocks (32-row segments) streaming denominator -> g_R ;
//              3 blocks template prep -> g_tA (aligned) + g_tB (shift-1)
//   (memcpy) : g_tA/g_tB -> __constant__ c_tA/c_tB
//   ncc_main : correlation, all fma.rn.f32x2; image rows via sliding 3-float4 smem
//              window, template rows via LDC. 64x32 tile, 8x2 px/thread.

#define EPSF 1e-9f
#define INV961 (1.0f/961.0f)
#define PLANE_ELEMS (24*1024*1024)
#define TSZ (3*31*32)

__device__ float g_tA[TSZ];
__device__ float g_tB[TSZ];
__device__ float g_R [PLANE_ELEMS];

__constant__ float c_tA[TSZ];
__constant__ float c_tB[TSZ];

__device__ __forceinline__ void dfma(float2 &d, const float2 a, const float2 b) {
    asm("fma.rn.f32x2 %0, %1, %2, %0;"
        : "+l"(reinterpret_cast<unsigned long long &>(d))
        : "l"(reinterpret_cast<const unsigned long long &>(a)),
          "l"(reinterpret_cast<const unsigned long long &>(b)));
}

// ---------------------------------------------------------------- aux: denom + prep
// C entry ci (0..1053) <-> image col ci-15. Padded smem index: ci + (ci>>2).
__global__ __launch_bounds__(256)
void ncc_aux(const float* __restrict__ img, const float* __restrict__ t) {
    const int b = blockIdx.x;
    const int tid = threadIdx.x;

    if (b >= 768) {                       // ---- template prep (3 blocks, warp 0) ----
        if (tid >= 32) return;
        const int c = b - 768;
        const int lane = tid;
        const float* tc = t + c * 961;
        float s = 0.f;
        for (int i = lane; i < 961; i += 32) s += tc[i];
#pragma unroll
        for (int o = 16; o > 0; o >>= 1) s += __shfl_xor_sync(0xffffffffu, s, o);
        const float mu = s * INV961;
        float v = 0.f;
        for (int i = lane; i < 961; i += 32) { float d = tc[i] - mu; v = fmaf(d, d, v); }
#pragma unroll
        for (int o = 16; o > 0; o >>= 1) v += __shfl_xor_sync(0xffffffffu, v, o);
        const float sd = sqrtf(v * INV961);
        const float scale = 1.f / ((sd + EPSF) * 961.f);
        for (int idx = lane; idx < 31 * 32; idx += 32) {
            const int ri = idx >> 5, j = idx & 31;
            g_tA[c * 992 + idx] = (j < 31) ? (tc[ri * 31 + j] - mu) * scale : 0.f;
            g_tB[c * 992 + idx] = (j < 30) ? (tc[ri * 31 + j + 1] - mu) * scale : 0.f;
        }
        return;
    }

    // ---- streaming denominator: one plane x 32-row segment per block ----
    __shared__ float C1[1320];
    __shared__ float C2[1320];
    const int pl = b >> 5, seg = b & 31;
    const int ry0 = seg << 5;
    const float* plane = img + ((size_t)pl << 20);

    for (int i = tid; i < 1320; i += 256) { C1[i] = 0.f; C2[i] = 0.f; }
    __syncthreads();

    for (int r = ry0 - 15; r <= ry0 + 15; ++r) {
        if ((unsigned)r >= 1024u) continue;
        const float* row = plane + ((size_t)r << 10);
        for (int ci = tid; ci < 1054; ci += 256) {
            const int col = ci - 15;
            if ((unsigned)col < 1024u) {
                const float v = row[col];
                const int pi = ci + (ci >> 2);
                C1[pi] += v;
                C2[pi] = fmaf(v, v, C2[pi]);
            }
        }
    }
    __syncthreads();

    const int x0 = tid << 2;
    float* Rseg = g_R + ((size_t)pl << 20) + x0;

#pragma unroll 1
    for (int y = ry0; y < ry0 + 32; ++y) {
        float S = 0.f, Q = 0.f, a0, a1, a2, b0, b1, b2;
#pragma unroll
        for (int j = 0; j < 31; ++j) {
            const int ci = x0 + j;
            const int pi = ci + (ci >> 2);
            const float c1v = C1[pi], c2v = C2[pi];
            S += c1v; Q += c2v;
            if (j == 0) { a0 = c1v; b0 = c2v; }
            if (j == 1) { a1 = c1v; b1 = c2v; }
            if (j == 2) { a2 = c1v; b2 = c2v; }
        }
        float n0, n1, n2, m0, m1v, m2v;
        {
            const int c31 = x0 + 31, c32 = x0 + 32, c33 = x0 + 33;
            n0 = C1[c31 + (c31 >> 2)]; m0  = C2[c31 + (c31 >> 2)];
            n1 = C1[c32 + (c32 >> 2)]; m1v = C2[c32 + (c32 >> 2)];
            n2 = C1[c33 + (c33 >> 2)]; m2v = C2[c33 + (c33 >> 2)];
        }
        const float s0 = S,            q0 = Q;
        const float s1 = s0 - a0 + n0, q1 = q0 - b0 + m0;
        const float s2 = s1 - a1 + n1, q2 = q1 - b1 + m1v;
        const float s3 = s2 - a2 + n2, q3 = q2 - b2 + m2v;

        float4 rv;
        { const float m = s0 * INV961; rv.x = 1.f / (sqrtf(fmaf(-m, m, q0 * INV961)) + EPSF); }
        { const float m = s1 * INV961; rv.y = 1.f / (sqrtf(fmaf(-m, m, q1 * INV961)) + EPSF); }
        { const float m = s2 * INV961; rv.z = 1.f / (sqrtf(fmaf(-m, m, q2 * INV961)) + EPSF); }
        { const float m = s3 * INV961; rv.w = 1.f / (sqrtf(fmaf(-m, m, q3 * INV961)) + EPSF); }
        *(float4*)(Rseg + ((size_t)y << 10)) = rv;

        __syncthreads();
        {
            const int ya = y + 16, ys = y - 15;
            const float* rowa = plane + ((size_t)ya << 10);
            const float* rows = plane + ((size_t)ys << 10);
            const bool va = (ya < 1024), vs = (ys >= 0);
            for (int ci = tid; ci < 1054; ci += 256) {
                const int col = ci - 15;
                if ((unsigned)col < 1024u) {
                    const float fa = va ? rowa[col] : 0.f;
                    const float fs = vs ? rows[col] : 0.f;
                    const int pi = ci + (ci >> 2);
                    C1[pi] += fa - fs;
                    C2[pi] += fa * fa - fs * fs;
                }
            }
        }
        __syncthreads();
    }
}

// ---------------------------------------------------------------- correlation row body
// Template rows come from __constant__ (LDC) at offsets toff0/toff1 (dual copies).
template<int DOP0, int DOP1>
__device__ __forceinline__ void corr_row2(
    const float* __restrict__ hrow, int toff0, int toff1,
    float2* __restrict__ acc0, float2* __restrict__ acc1)
{
    float4 W0 = *(const float4*)(hrow);
    float4 W1 = *(const float4*)(hrow + 4);
    const float w1s = W0.y, w3s = W0.w, w5s = W1.y, w7s = W1.w;
#pragma unroll
    for (int q = 0; q < 8; ++q) {
        const float4 W2 = *(const float4*)(hrow + 8 + (q << 2));
        const float2 P0 = make_float2(W0.x, W0.y), P1 = make_float2(W0.z, W0.w);
        const float2 P2 = make_float2(W1.x, W1.y), P3 = make_float2(W1.z, W1.w);
        const float2 P4 = make_float2(W2.x, W2.y), P5 = make_float2(W2.z, W2.w);
        if (DOP0) {
            const float4 ta = *(const float4*)(c_tA + toff0 + (q << 2));
            const float4 tb = *(const float4*)(c_tB + toff0 + (q << 2));
            const float2 A0 = make_float2(ta.x, ta.y), A1 = make_float2(ta.z, ta.w);
            const float2 B0 = make_float2(tb.x, tb.y), B1 = make_float2(tb.z, tb.w);
            dfma(acc0[0], P0, A0); dfma(acc0[2], P1, A0); dfma(acc0[4], P2, A0); dfma(acc0[6], P3, A0);
            dfma(acc0[1], P1, B0); dfma(acc0[3], P2, B0); dfma(acc0[5], P3, B0); dfma(acc0[7], P4, B0);
            dfma(acc0[0], P1, A1); dfma(acc0[2], P2, A1); dfma(acc0[4], P3, A1); dfma(acc0[6], P4, A1);
            dfma(acc0[1], P2, B1); dfma(acc0[3], P3, B1); dfma(acc0[5], P4, B1); dfma(acc0[7], P5, B1);
        }
        if (DOP1) {
            const float4 ta = *(const float4*)(c_tA + toff1 + (q << 2));
            const float4 tb = *(const float4*)(c_tB + toff1 + (q << 2));
            const float2 A0 = make_float2(ta.x, ta.y), A1 = make_float2(ta.z, ta.w);
            const float2 B0 = make_float2(tb.x, tb.y), B1 = make_float2(tb.z, tb.w);
            dfma(acc1[0], P0, A0); dfma(acc1[2], P1, A0); dfma(acc1[4], P2, A0); dfma(acc1[6], P3, A0);
            dfma(acc1[1], P1, B0); dfma(acc1[3], P2, B0); dfma(acc1[5], P3, B0); dfma(acc1[7], P4, B0);
            dfma(acc1[0], P1, A1); dfma(acc1[2], P2, A1); dfma(acc1[4], P3, A1); dfma(acc1[6], P4, A1);
            dfma(acc1[1], P2, B1); dfma(acc1[3], P3, B1); dfma(acc1[5], P4, B1); dfma(acc1[7], P5, B1);
        }
        W0 = W1; W1 = W2;
    }
    if (DOP0) {
        const float t0 = c_tA[toff0];   // tap(0) scalar for odd pixels (shifted template)
        acc0[1].x = fmaf(w1s, t0, acc0[1].x);
        acc0[3].x = fmaf(w3s, t0, acc0[3].x);
        acc0[5].x = fmaf(w5s, t0, acc0[5].x);
        acc0[7].x = fmaf(w7s, t0, acc0[7].x);
    }
    if (DOP1) {
        const float t0 = c_tA[toff1];
        acc1[1].x = fmaf(w1s, t0, acc1[1].x);
        acc1[3].x = fmaf(w3s, t0, acc1[3].x);
        acc1[5].x = fmaf(w5s, t0, acc1[5].x);
        acc1[7].x = fmaf(w7s, t0, acc1[7].x);
    }
}

// ---------------------------------------------------------------- main correlation
__global__ __launch_bounds__(128, 5)
void ncc_main(const float* __restrict__ img, float* __restrict__ out) {
    __shared__ __align__(16) float sh_halo[62][100];    // cols 0..95 valid, stride 100
    __shared__ float sh_oacc[16][128];                  // cross-channel accum, col per thread

    const int tx = threadIdx.x;           // 0..7
    const int ty = threadIdx.y;           // 0..15
    const int tid = ty * 8 + tx;
    const int bx = blockIdx.x, by = blockIdx.y, n = blockIdx.z;
    const int gx0 = bx << 6, gy0 = by << 5;
    const int x0 = tx << 3, y0 = ty << 1;  // 8 wide x 2 tall per thread

    // zero the cross-channel accumulator (thread-private columns; no sync needed)
#pragma unroll
    for (int j = 0; j < 16; ++j) sh_oacc[j][tid] = 0.f;

    for (int c = 0; c < 3; ++c) {
        __syncthreads();
        // halo: 62 rows x 96 cols (zero outside image)
        if (tid < 96) {
            const float* plane = img + ((size_t)(n * 3 + c) << 20);
            const int gx = gx0 - 15 + tid;
            const bool xok = (unsigned)gx < 1024u;
#pragma unroll 1
            for (int r = 0; r < 62; ++r) {
                const int gy = gy0 - 15 + r;
                float v = 0.f;
                if (xok && ((unsigned)gy < 1024u)) v = plane[((size_t)gy << 10) + gx];
                sh_halo[r][tid] = v;
            }
        }
        __syncthreads();

        float2 acc0[8], acc1[8];
#pragma unroll
        for (int k = 0; k < 8; ++k) { acc0[k] = make_float2(0.f, 0.f); acc1[k] = make_float2(0.f, 0.f); }

        const int tc0 = c * 992;
        // r=0: only p=0 (template row 0); r=1..30: both; r=31: only p=1 (template row 30)
        corr_row2<1, 0>(&sh_halo[y0][x0], tc0, tc0, acc0, acc1);
#pragma unroll 1
        for (int r = 1; r < 31; ++r) {
            corr_row2<1, 1>(&sh_halo[y0 + r][x0],
                            tc0 + (r << 5), tc0 + ((r - 1) << 5), acc0, acc1);
        }
        corr_row2<0, 1>(&sh_halo[y0 + 31][x0], tc0, tc0 + (30 << 5), acc0, acc1);

        // combine with precomputed reciprocal denominator into smem oacc
        {
            const float* Rpl = g_R + ((size_t)(n * 3 + c) << 20);
            {
                const float* rp = Rpl + ((size_t)(gy0 + y0) << 10) + gx0 + x0;
                const float4 r0 = *(const float4*)rp;
                const float4 r1 = *(const float4*)(rp + 4);
                sh_oacc[0][tid] += (acc0[0].x + acc0[0].y) * r0.x;
                sh_oacc[1][tid] += (acc0[1].x + acc0[1].y) * r0.y;
                sh_oacc[2][tid] += (acc0[2].x + acc0[2].y) * r0.z;
                sh_oacc[3][tid] += (acc0[3].x + acc0[3].y) * r0.w;
                sh_oacc[4][tid] += (acc0[4].x + acc0[4].y) * r1.x;
                sh_oacc[5][tid] += (acc0[5].x + acc0[5].y) * r1.y;
                sh_oacc[6][tid] += (acc0[6].x + acc0[6].y) * r1.z;
                sh_oacc[7][tid] += (acc0[7].x + acc0[7].y) * r1.w;
            }
            {
                const float* rp = Rpl + ((size_t)(gy0 + y0 + 1) << 10) + gx0 + x0;
                const float4 r0 = *(const float4*)rp;
                const float4 r1 = *(const float4*)(rp + 4);
                sh_oacc[8][tid]  += (acc1[0].x + acc1[0].y) * r0.x;
                sh_oacc[9][tid]  += (acc1[1].x + acc1[1].y) * r0.y;
                sh_oacc[10][tid] += (acc1[2].x + acc1[2].y) * r0.z;
                sh_oacc[11][tid] += (acc1[3].x + acc1[3].y) * r0.w;
                sh_oacc[12][tid] += (acc1[4].x + acc1[4].y) * r1.x;
                sh_oacc[13][tid] += (acc1[5].x + acc1[5].y) * r1.y;
                sh_oacc[14][tid] += (acc1[6].x + acc1[6].y) * r1.z;
                sh_oacc[15][tid] += (acc1[7].x + acc1[7].y) * r1.w;
            }
        }
    }

    // write out: mean over channels, NaN -> 0
#pragma unroll
    for (int p = 0; p < 2; ++p) {
        float v[8];
#pragma unroll
        for (int k = 0; k < 8; ++k) {
            const float r = sh_oacc[p * 8 + k][tid] * (1.0f / 3.0f);
            v[k] = (r == r) ? r : 0.f;
        }
        float* dst = out + (((size_t)n << 20) + ((size_t)(gy0 + y0 + p) << 10) + gx0 + x0);
        *(float4*)dst       = make_float4(v[0], v[1], v[2], v[3]);
        *(float4*)(dst + 4) = make_float4(v[4], v[5], v[6], v[7]);
    }
}

extern "C" void kernel_launch(void* const* d_in, const int* in_sizes, int n_in,
                              void* d_out, int out_size) {
    (void)in_sizes; (void)n_in; (void)out_size;
    const float* img  = (const float*)d_in[0];
    const float* tmpl = (const float*)d_in[1];
    float* out = (float*)d_out;

    ncc_aux<<<771, 256>>>(img, tmpl);                       // denom (768) + prep (3)

    // copy normalized template into constant memory (graph-legal async D2D)
    void *pA = nullptr, *pB = nullptr, *gA = nullptr, *gB = nullptr;
    cudaGetSymbolAddress(&pA, c_tA);
    cudaGetSymbolAddress(&pB, c_tB);
    cudaGetSymbolAddress(&gA, g_tA);
    cudaGetSymbolAddress(&gB, g_tB);
    cudaMemcpyAsync(pA, gA, TSZ * sizeof(float), cudaMemcpyDeviceToDevice);
    cudaMemcpyAsync(pB, gB, TSZ * sizeof(float), cudaMemcpyDeviceToDevice);

    ncc_main<<<dim3(16, 32, 8), dim3(8, 16)>>>(img, out);
}

// round 16
// speedup vs baseline: 1.6453x; 1.0017x over previous
#include <cuda_runtime.h>

// NCC: image (8,3,1024,1024) f32, template (3,31,31) f32, stride 1, pad 15.
// out (8,1024,1024) f32 = mean_c[ conv(img, norm_t) / (sqrt(m2-m1^2)+eps) ], NaN->0
//
// R16 = R15 resubmitted verbatim (R15 never ran: broker container failure).
//   Template split across BOTH uniform-load ports:
//   tA (aligned copy)  -> __constant__  (16 LDC.128/row, const port @ 47% of FMA time)
//   tB (shift-1 copy)  -> smem          (16 LDS.128/row, warp-uniform broadcast)
//   -> FMA pipe becomes the sole binding resource.
//   ncc_aux  : 768 blocks (32-row segments) streaming denominator -> g_R ;
//              3 blocks template prep -> g_tA + g_tB
//   ncc_main : correlation, all fma.rn.f32x2; (128,5), 20 warps/SM.

#define EPSF 1e-9f
#define INV961 (1.0f/961.0f)
#define PLANE_ELEMS (24*1024*1024)
#define TSZ (3*31*32)

__device__ float g_tA[TSZ];
__device__ float g_tB[TSZ];
__device__ float g_R [PLANE_ELEMS];

__constant__ float c_tA[TSZ];

__device__ __forceinline__ void dfma(float2 &d, const float2 a, const float2 b) {
    asm("fma.rn.f32x2 %0, %1, %2, %0;"
        : "+l"(reinterpret_cast<unsigned long long &>(d))
        : "l"(reinterpret_cast<const unsigned long long &>(a)),
          "l"(reinterpret_cast<const unsigned long long &>(b)));
}

// ---------------------------------------------------------------- aux: denom + prep
// C entry ci (0..1053) <-> image col ci-15. Padded smem index: ci + (ci>>2).
__global__ __launch_bounds__(256)
void ncc_aux(const float* __restrict__ img, const float* __restrict__ t) {
    const int b = blockIdx.x;
    const int tid = threadIdx.x;

    if (b >= 768) {                       // ---- template prep (3 blocks, warp 0) ----
        if (tid >= 32) return;
        const int c = b - 768;
        const int lane = tid;
        const float* tc = t + c * 961;
        float s = 0.f;
        for (int i = lane; i < 961; i += 32) s += tc[i];
#pragma unroll
        for (int o = 16; o > 0; o >>= 1) s += __shfl_xor_sync(0xffffffffu, s, o);
        const float mu = s * INV961;
        float v = 0.f;
        for (int i = lane; i < 961; i += 32) { float d = tc[i] - mu; v = fmaf(d, d, v); }
#pragma unroll
        for (int o = 16; o > 0; o >>= 1) v += __shfl_xor_sync(0xffffffffu, v, o);
        const float sd = sqrtf(v * INV961);
        const float scale = 1.f / ((sd + EPSF) * 961.f);
        for (int idx = lane; idx < 31 * 32; idx += 32) {
            const int ri = idx >> 5, j = idx & 31;
            g_tA[c * 992 + idx] = (j < 31) ? (tc[ri * 31 + j] - mu) * scale : 0.f;
            g_tB[c * 992 + idx] = (j < 30) ? (tc[ri * 31 + j + 1] - mu) * scale : 0.f;
        }
        return;
    }

    // ---- streaming denominator: one plane x 32-row segment per block ----
    __shared__ float C1[1320];
    __shared__ float C2[1320];
    const int pl = b >> 5, seg = b & 31;
    const int ry0 = seg << 5;
    const float* plane = img + ((size_t)pl << 20);

    for (int i = tid; i < 1320; i += 256) { C1[i] = 0.f; C2[i] = 0.f; }
    __syncthreads();

    for (int r = ry0 - 15; r <= ry0 + 15; ++r) {
        if ((unsigned)r >= 1024u) continue;
        const float* row = plane + ((size_t)r << 10);
        for (int ci = tid; ci < 1054; ci += 256) {
            const int col = ci - 15;
            if ((unsigned)col < 1024u) {
                const float v = row[col];
                const int pi = ci + (ci >> 2);
                C1[pi] += v;
                C2[pi] = fmaf(v, v, C2[pi]);
            }
        }
    }
    __syncthreads();

    const int x0 = tid << 2;
    float* Rseg = g_R + ((size_t)pl << 20) + x0;

#pragma unroll 1
    for (int y = ry0; y < ry0 + 32; ++y) {
        float S = 0.f, Q = 0.f, a0, a1, a2, b0, b1, b2;
#pragma unroll
        for (int j = 0; j < 31; ++j) {
            const int ci = x0 + j;
            const int pi = ci + (ci >> 2);
            const float c1v = C1[pi], c2v = C2[pi];
            S += c1v; Q += c2v;
            if (j == 0) { a0 = c1v; b0 = c2v; }
            if (j == 1) { a1 = c1v; b1 = c2v; }
            if (j == 2) { a2 = c1v; b2 = c2v; }
        }
        float n0, n1, n2, m0, m1v, m2v;
        {
            const int c31 = x0 + 31, c32 = x0 + 32, c33 = x0 + 33;
            n0 = C1[c31 + (c31 >> 2)]; m0  = C2[c31 + (c31 >> 2)];
            n1 = C1[c32 + (c32 >> 2)]; m1v = C2[c32 + (c32 >> 2)];
            n2 = C1[c33 + (c33 >> 2)]; m2v = C2[c33 + (c33 >> 2)];
        }
        const float s0 = S,            q0 = Q;
        const float s1 = s0 - a0 + n0, q1 = q0 - b0 + m0;
        const float s2 = s1 - a1 + n1, q2 = q1 - b1 + m1v;
        const float s3 = s2 - a2 + n2, q3 = q2 - b2 + m2v;

        float4 rv;
        { const float m = s0 * INV961; rv.x = 1.f / (sqrtf(fmaf(-m, m, q0 * INV961)) + EPSF); }
        { const float m = s1 * INV961; rv.y = 1.f / (sqrtf(fmaf(-m, m, q1 * INV961)) + EPSF); }
        { const float m = s2 * INV961; rv.z = 1.f / (sqrtf(fmaf(-m, m, q2 * INV961)) + EPSF); }
        { const float m = s3 * INV961; rv.w = 1.f / (sqrtf(fmaf(-m, m, q3 * INV961)) + EPSF); }
        *(float4*)(Rseg + ((size_t)y << 10)) = rv;

        __syncthreads();
        {
            const int ya = y + 16, ys = y - 15;
            const float* rowa = plane + ((size_t)ya << 10);
            const float* rows = plane + ((size_t)ys << 10);
            const bool va = (ya < 1024), vs = (ys >= 0);
            for (int ci = tid; ci < 1054; ci += 256) {
                const int col = ci - 15;
                if ((unsigned)col < 1024u) {
                    const float fa = va ? rowa[col] : 0.f;
                    const float fs = vs ? rows[col] : 0.f;
                    const int pi = ci + (ci >> 2);
                    C1[pi] += fa - fs;
                    C2[pi] += fa * fa - fs * fs;
                }
            }
        }
        __syncthreads();
    }
}

// ---------------------------------------------------------------- correlation row body
// tA rows from __constant__ (LDC) at offsets toff0/toff1 (include channel);
// tB rows from smem (warp-uniform broadcast LDS) via pointers tb0/tb1.
template<int DOP0, int DOP1>
__device__ __forceinline__ void corr_row2(
    const float* __restrict__ hrow, int toff0, int toff1,
    const float* __restrict__ tb0, const float* __restrict__ tb1,
    float2* __restrict__ acc0, float2* __restrict__ acc1)
{
    float4 W0 = *(const float4*)(hrow);
    float4 W1 = *(const float4*)(hrow + 4);
    const float w1s = W0.y, w3s = W0.w, w5s = W1.y, w7s = W1.w;
#pragma unroll
    for (int q = 0; q < 8; ++q) {
        const float4 W2 = *(const float4*)(hrow + 8 + (q << 2));
        const float2 P0 = make_float2(W0.x, W0.y), P1 = make_float2(W0.z, W0.w);
        const float2 P2 = make_float2(W1.x, W1.y), P3 = make_float2(W1.z, W1.w);
        const float2 P4 = make_float2(W2.x, W2.y), P5 = make_float2(W2.z, W2.w);
        if (DOP0) {
            const float4 ta = *(const float4*)(c_tA + toff0 + (q << 2));
            const float4 tb = *(const float4*)(tb0 + (q << 2));
            const float2 A0 = make_float2(ta.x, ta.y), A1 = make_float2(ta.z, ta.w);
            const float2 B0 = make_float2(tb.x, tb.y), B1 = make_float2(tb.z, tb.w);
            dfma(acc0[0], P0, A0); dfma(acc0[2], P1, A0); dfma(acc0[4], P2, A0); dfma(acc0[6], P3, A0);
            dfma(acc0[1], P1, B0); dfma(acc0[3], P2, B0); dfma(acc0[5], P3, B0); dfma(acc0[7], P4, B0);
            dfma(acc0[0], P1, A1); dfma(acc0[2], P2, A1); dfma(acc0[4], P3, A1); dfma(acc0[6], P4, A1);
            dfma(acc0[1], P2, B1); dfma(acc0[3], P3, B1); dfma(acc0[5], P4, B1); dfma(acc0[7], P5, B1);
        }
        if (DOP1) {
            const float4 ta = *(const float4*)(c_tA + toff1 + (q << 2));
            const float4 tb = *(const float4*)(tb1 + (q << 2));
            const float2 A0 = make_float2(ta.x, ta.y), A1 = make_float2(ta.z, ta.w);
            const float2 B0 = make_float2(tb.x, tb.y), B1 = make_float2(tb.z, tb.w);
            dfma(acc1[0], P0, A0); dfma(acc1[2], P1, A0); dfma(acc1[4], P2, A0); dfma(acc1[6], P3, A0);
            dfma(acc1[1], P1, B0); dfma(acc1[3], P2, B0); dfma(acc1[5], P3, B0); dfma(acc1[7], P4, B0);
            dfma(acc1[0], P1, A1); dfma(acc1[2], P2, A1); dfma(acc1[4], P3, A1); dfma(acc1[6], P4, A1);
            dfma(acc1[1], P2, B1); dfma(acc1[3], P3, B1); dfma(acc1[5], P4, B1); dfma(acc1[7], P5, B1);
        }
        W0 = W1; W1 = W2;
    }
    if (DOP0) {
        const float t0 = c_tA[toff0];   // tap(0) scalar for odd pixels (shifted template)
        acc0[1].x = fmaf(w1s, t0, acc0[1].x);
        acc0[3].x = fmaf(w3s, t0, acc0[3].x);
        acc0[5].x = fmaf(w5s, t0, acc0[5].x);
        acc0[7].x = fmaf(w7s, t0, acc0[7].x);
    }
    if (DOP1) {
        const float t0 = c_tA[toff1];
        acc1[1].x = fmaf(w1s, t0, acc1[1].x);
        acc1[3].x = fmaf(w3s, t0, acc1[3].x);
        acc1[5].x = fmaf(w5s, t0, acc1[5].x);
        acc1[7].x = fmaf(w7s, t0, acc1[7].x);
    }
}

// ---------------------------------------------------------------- main correlation
__global__ __launch_bounds__(128, 5)
void ncc_main(const float* __restrict__ img, float* __restrict__ out) {
    __shared__ __align__(16) float sh_halo[62][100];    // cols 0..95 valid, stride 100
    __shared__ float sh_oacc[16][128];                  // cross-channel accum, col per thread
    __shared__ __align__(16) float sh_tB[992];          // shifted template copy (this channel)

    const int tx = threadIdx.x;           // 0..7
    const int ty = threadIdx.y;           // 0..15
    const int tid = ty * 8 + tx;
    const int bx = blockIdx.x, by = blockIdx.y, n = blockIdx.z;
    const int gx0 = bx << 6, gy0 = by << 5;
    const int x0 = tx << 3, y0 = ty << 1;  // 8 wide x 2 tall per thread

    // zero the cross-channel accumulator (thread-private columns; no sync needed)
#pragma unroll
    for (int j = 0; j < 16; ++j) sh_oacc[j][tid] = 0.f;

    for (int c = 0; c < 3; ++c) {
        __syncthreads();
        // shifted template copy for this channel -> smem
#pragma unroll
        for (int i = 0; i < 8; ++i) {
            const int idx = tid + (i << 7);
            if (idx < 992) sh_tB[idx] = g_tB[c * 992 + idx];
        }
        // halo: 62 rows x 96 cols (zero outside image)
        if (tid < 96) {
            const float* plane = img + ((size_t)(n * 3 + c) << 20);
            const int gx = gx0 - 15 + tid;
            const bool xok = (unsigned)gx < 1024u;
#pragma unroll 1
            for (int r = 0; r < 62; ++r) {
                const int gy = gy0 - 15 + r;
                float v = 0.f;
                if (xok && ((unsigned)gy < 1024u)) v = plane[((size_t)gy << 10) + gx];
                sh_halo[r][tid] = v;
            }
        }
        __syncthreads();

        float2 acc0[8], acc1[8];
#pragma unroll
        for (int k = 0; k < 8; ++k) { acc0[k] = make_float2(0.f, 0.f); acc1[k] = make_float2(0.f, 0.f); }

        const int tc0 = c * 992;
        // r=0: only p=0 (template row 0); r=1..30: both; r=31: only p=1 (template row 30)
        corr_row2<1, 0>(&sh_halo[y0][x0], tc0, tc0, sh_tB, sh_tB, acc0, acc1);
#pragma unroll 1
        for (int r = 1; r < 31; ++r) {
            corr_row2<1, 1>(&sh_halo[y0 + r][x0],
                            tc0 + (r << 5), tc0 + ((r - 1) << 5),
                            sh_tB + (r << 5), sh_tB + ((r - 1) << 5),
                            acc0, acc1);
        }
        corr_row2<0, 1>(&sh_halo[y0 + 31][x0], tc0, tc0 + (30 << 5),
                        sh_tB, sh_tB + (30 << 5), acc0, acc1);

        // combine with precomputed reciprocal denominator into smem oacc
        {
            const float* Rpl = g_R + ((size_t)(n * 3 + c) << 20);
            {
                const float* rp = Rpl + ((size_t)(gy0 + y0) << 10) + gx0 + x0;
                const float4 r0 = *(const float4*)rp;
                const float4 r1 = *(const float4*)(rp + 4);
                sh_oacc[0][tid] += (acc0[0].x + acc0[0].y) * r0.x;
                sh_oacc[1][tid] += (acc0[1].x + acc0[1].y) * r0.y;
                sh_oacc[2][tid] += (acc0[2].x + acc0[2].y) * r0.z;
                sh_oacc[3][tid] += (acc0[3].x + acc0[3].y) * r0.w;
                sh_oacc[4][tid] += (acc0[4].x + acc0[4].y) * r1.x;
                sh_oacc[5][tid] += (acc0[5].x + acc0[5].y) * r1.y;
                sh_oacc[6][tid] += (acc0[6].x + acc0[6].y) * r1.z;
                sh_oacc[7][tid] += (acc0[7].x + acc0[7].y) * r1.w;
            }
            {
                const float* rp = Rpl + ((size_t)(gy0 + y0 + 1) << 10) + gx0 + x0;
                const float4 r0 = *(const float4*)rp;
                const float4 r1 = *(const float4*)(rp + 4);
                sh_oacc[8][tid]  += (acc1[0].x + acc1[0].y) * r0.x;
                sh_oacc[9][tid]  += (acc1[1].x + acc1[1].y) * r0.y;
                sh_oacc[10][tid] += (acc1[2].x + acc1[2].y) * r0.z;
                sh_oacc[11][tid] += (acc1[3].x + acc1[3].y) * r0.w;
                sh_oacc[12][tid] += (acc1[4].x + acc1[4].y) * r1.x;
                sh_oacc[13][tid] += (acc1[5].x + acc1[5].y) * r1.y;
                sh_oacc[14][tid] += (acc1[6].x + acc1[6].y) * r1.z;
                sh_oacc[15][tid] += (acc1[7].x + acc1[7].y) * r1.w;
            }
        }
    }

    // write out: mean over channels, NaN -> 0
#pragma unroll
    for (int p = 0; p < 2; ++p) {
        float v[8];
#pragma unroll
        for (int k = 0; k < 8; ++k) {
            const float r = sh_oacc[p * 8 + k][tid] * (1.0f / 3.0f);
            v[k] = (r == r) ? r : 0.f;
        }
        float* dst = out + (((size_t)n << 20) + ((size_t)(gy0 + y0 + p) << 10) + gx0 + x0);
        *(float4*)dst       = make_float4(v[0], v[1], v[2], v[3]);
        *(float4*)(dst + 4) = make_float4(v[4], v[5], v[6], v[7]);
    }
}

extern "C" void kernel_launch(void* const* d_in, const int* in_sizes, int n_in,
                              void* d_out, int out_size) {
    (void)in_sizes; (void)n_in; (void)out_size;
    const float* img  = (const float*)d_in[0];
    const float* tmpl = (const float*)d_in[1];
    float* out = (float*)d_out;

    ncc_aux<<<771, 256>>>(img, tmpl);                       // denom (768) + prep (3)

    // copy aligned template copy into constant memory (graph-legal async D2D)
    void *pA = nullptr, *gA = nullptr;
    cudaGetSymbolAddress(&pA, c_tA);
    cudaGetSymbolAddress(&gA, g_tA);
    cudaMemcpyAsync(pA, gA, TSZ * sizeof(float), cudaMemcpyDeviceToDevice);

    ncc_main<<<dim3(16, 32, 8), dim3(8, 16)>>>(img, out);
}